// round 1
// baseline (speedup 1.0000x reference)
#include <cuda_runtime.h>

#define BATCH 4
#define SEQ 1024
#define NHEADS 16
#define HDIM 64
#define BHD (BATCH*NHEADS)          // 64
#define QKV_ELEMS (BATCH*NHEADS*SEQ*HDIM)  // 4,194,304

__device__ float g_q[QKV_ELEMS];
__device__ float g_k[QKV_ELEMS];
__device__ float g_v[QKV_ELEMS];

// ---------------------------------------------------------------------------
// Kernel 1: QKV projection  C[n,o] = sum_i A[n,i]*W[o,i] + bias[o]
// A = hidden [4096,1024], W = [3072,1024]. Scatter into g_q/g_k/g_v [B,h,S,d].
// ---------------------------------------------------------------------------
__global__ __launch_bounds__(256, 2) void qkv_gemm_kernel(
    const float* __restrict__ A,
    const float* __restrict__ W,
    const float* __restrict__ bias)
{
    __shared__ float As[8][128];
    __shared__ float Ws[8][128];

    const int bm = blockIdx.y * 128;   // n tile
    const int bn = blockIdx.x * 128;   // o tile
    const int tid = threadIdx.x;
    const int tx = tid & 15;
    const int ty = tid >> 4;
    const int lr = tid >> 1;           // 0..127
    const int lc = (tid & 1) * 4;      // 0 or 4

    float acc[8][8];
#pragma unroll
    for (int i = 0; i < 8; i++)
#pragma unroll
        for (int j = 0; j < 8; j++) acc[i][j] = 0.f;

    const float* Aptr = A + (size_t)(bm + lr) * 1024 + lc;
    const float* Wptr = W + (size_t)(bn + lr) * 1024 + lc;

    for (int k0 = 0; k0 < 1024; k0 += 8) {
        float4 a = *(const float4*)(Aptr + k0);
        float4 w = *(const float4*)(Wptr + k0);
        __syncthreads();
        As[lc + 0][lr] = a.x; As[lc + 1][lr] = a.y;
        As[lc + 2][lr] = a.z; As[lc + 3][lr] = a.w;
        Ws[lc + 0][lr] = w.x; Ws[lc + 1][lr] = w.y;
        Ws[lc + 2][lr] = w.z; Ws[lc + 3][lr] = w.w;
        __syncthreads();
#pragma unroll
        for (int kk = 0; kk < 8; kk++) {
            float4 a0 = *(const float4*)&As[kk][ty * 4];
            float4 a1 = *(const float4*)&As[kk][64 + ty * 4];
            float4 w0 = *(const float4*)&Ws[kk][tx * 4];
            float4 w1 = *(const float4*)&Ws[kk][64 + tx * 4];
            float af[8] = {a0.x, a0.y, a0.z, a0.w, a1.x, a1.y, a1.z, a1.w};
            float wf[8] = {w0.x, w0.y, w0.z, w0.w, w1.x, w1.y, w1.z, w1.w};
#pragma unroll
            for (int i = 0; i < 8; i++)
#pragma unroll
                for (int j = 0; j < 8; j++)
                    acc[i][j] += af[i] * wf[j];
        }
    }

#pragma unroll
    for (int i = 0; i < 8; i++) {
        int n = bm + ((i < 4) ? (ty * 4 + i) : (64 + ty * 4 + i - 4));
        int b = n >> 10;
        int s = n & 1023;
#pragma unroll
        for (int j = 0; j < 8; j++) {
            int o = bn + ((j < 4) ? (tx * 4 + j) : (64 + tx * 4 + j - 4));
            float c = acc[i][j] + bias[o];
            int t = o >> 10;        // 0=q,1=k,2=v
            int oo = o & 1023;
            int head = oo >> 6;
            int dd = oo & 63;
            float* dst = (t == 0) ? g_q : (t == 1) ? g_k : g_v;
            dst[(((b << 4) + head) << 16) | (s << 6) | dd] = c;
        }
    }
}

// ---------------------------------------------------------------------------
// Kernel 2: fused attention with relative_key_query bias.
// scores[l,r] = q_l·k_r + (q_l + k_r)·D[l-r+1023], /8, +mask, softmax, @V
// One block = one (b,h) x 64-query-row tile. 256 threads, 4x4 micro-tiles.
// Shared memory (dynamic, 98304 B):
//   qs[64][64]  (qs[d][i])     0
//   ks[64][64]  (ks[d][j])     4096
//   vs[64][64]  (vs[r][d])     8192
//   Ds[64][128] (Ds[d][delta]) 12288
//   Ps[64][64]  (Ps[i][r])     20480
// ---------------------------------------------------------------------------
__global__ __launch_bounds__(256, 2) void attn_kernel(
    const float* __restrict__ dist,   // [2047,64]
    const float* __restrict__ mask,   // [B,1,1,S]
    float* __restrict__ out)          // [B,S,1024]
{
    extern __shared__ float sm[];
    float* qs = sm;
    float* ks = sm + 4096;
    float* vs = sm + 8192;
    float* Ds = sm + 12288;
    float* Ps = sm + 20480;

    const int l0 = blockIdx.x * 64;
    const int bh = blockIdx.y;
    const int b  = bh >> 4;
    const int h  = bh & 15;
    const int tid = threadIdx.x;
    const int tx = tid & 15;
    const int ty = tid >> 4;
    const int i0 = ty * 4;
    const int j0 = tx * 4;
    const int dbase = i0 - j0 + 60;   // in [0,120], multiple of 4

    const float* qg = g_q + (size_t)bh * (SEQ * HDIM);
    const float* kg = g_k + (size_t)bh * (SEQ * HDIM);
    const float* vg = g_v + (size_t)bh * (SEQ * HDIM);

    // load q tile transposed: qs[d][i]
    {
        int irow = tid >> 2;
        int d0 = (tid & 3) * 16;
#pragma unroll
        for (int c = 0; c < 4; c++) {
            int d = d0 + c * 4;
            float4 q4 = *(const float4*)&qg[(l0 + irow) * 64 + d];
            qs[(d + 0) * 64 + irow] = q4.x;
            qs[(d + 1) * 64 + irow] = q4.y;
            qs[(d + 2) * 64 + irow] = q4.z;
            qs[(d + 3) * 64 + irow] = q4.w;
        }
    }

    float O[4][4];
    float m[4], l[4];
#pragma unroll
    for (int i = 0; i < 4; i++) {
        m[i] = -1e30f; l[i] = 0.f;
#pragma unroll
        for (int j = 0; j < 4; j++) O[i][j] = 0.f;
    }

    for (int r0 = 0; r0 < SEQ; r0 += 64) {
        __syncthreads();   // protects vs/ks/Ds/Ps from previous iteration
        // load k (transposed), v (natural)
        {
            int jrow = tid >> 2;
            int d0 = (tid & 3) * 16;
#pragma unroll
            for (int c = 0; c < 4; c++) {
                int d = d0 + c * 4;
                float4 k4 = *(const float4*)&kg[(r0 + jrow) * 64 + d];
                ks[(d + 0) * 64 + jrow] = k4.x;
                ks[(d + 1) * 64 + jrow] = k4.y;
                ks[(d + 2) * 64 + jrow] = k4.z;
                ks[(d + 3) * 64 + jrow] = k4.w;
                float4 v4 = *(const float4*)&vg[(r0 + jrow) * 64 + d];
                *(float4*)&vs[jrow * 64 + d] = v4;
            }
            // D band: rows jb .. jb+126 of dist, transposed: Ds[d][delta]
            int jb = l0 - r0 + 960;
#pragma unroll
            for (int it = 0; it < 2; it++) {
                int delta = (tid >> 2) + it * 64;
                if (delta < 127) {
                    int dd0 = (tid & 3) * 16;
#pragma unroll
                    for (int c = 0; c < 4; c++) {
                        int d = dd0 + c * 4;
                        float4 p4 = *(const float4*)&dist[(jb + delta) * 64 + d];
                        Ds[(d + 0) * 128 + delta] = p4.x;
                        Ds[(d + 1) * 128 + delta] = p4.y;
                        Ds[(d + 2) * 128 + delta] = p4.z;
                        Ds[(d + 3) * 128 + delta] = p4.w;
                    }
                }
            }
        }
        __syncthreads();

        // ---- scores: acc[i][j] = q·k + (q+k)·D ----
        float acc[4][4];
#pragma unroll
        for (int i = 0; i < 4; i++)
#pragma unroll
            for (int j = 0; j < 4; j++) acc[i][j] = 0.f;

#pragma unroll 8
        for (int d = 0; d < 64; d++) {
            float4 qf = *(const float4*)&qs[d * 64 + i0];
            float4 kf = *(const float4*)&ks[d * 64 + j0];
            float4 d0f = *(const float4*)&Ds[d * 128 + dbase];
            float4 d1f = *(const float4*)&Ds[d * 128 + dbase + 4];
            float qa[4] = {qf.x, qf.y, qf.z, qf.w};
            float ka[4] = {kf.x, kf.y, kf.z, kf.w};
            float da[8] = {d0f.x, d0f.y, d0f.z, d0f.w, d1f.x, d1f.y, d1f.z, d1f.w};
#pragma unroll
            for (int di = 0; di < 4; di++)
#pragma unroll
                for (int dj = 0; dj < 4; dj++) {
                    float dv = da[di - dj + 3];
                    acc[di][dj] += qa[di] * (ka[dj] + dv) + ka[dj] * dv;
                }
        }

        // ---- online softmax ----
        float4 mk4 = *(const float4*)&mask[b * SEQ + r0 + j0];
        float mk[4] = {mk4.x, mk4.y, mk4.z, mk4.w};
        float p[4][4];
#pragma unroll
        for (int di = 0; di < 4; di++) {
            float s_[4];
#pragma unroll
            for (int dj = 0; dj < 4; dj++)
                s_[dj] = acc[di][dj] * 0.125f + mk[dj];
            float rmax = fmaxf(fmaxf(s_[0], s_[1]), fmaxf(s_[2], s_[3]));
#pragma unroll
            for (int off = 1; off < 16; off <<= 1)
                rmax = fmaxf(rmax, __shfl_xor_sync(0xffffffffu, rmax, off));
            float mnew = fmaxf(m[di], rmax);
            float corr = __expf(m[di] - mnew);
            float rsum = 0.f;
#pragma unroll
            for (int dj = 0; dj < 4; dj++) {
                p[di][dj] = __expf(s_[dj] - mnew);
                rsum += p[di][dj];
            }
#pragma unroll
            for (int off = 1; off < 16; off <<= 1)
                rsum += __shfl_xor_sync(0xffffffffu, rsum, off);
            l[di] = l[di] * corr + rsum;
            m[di] = mnew;
#pragma unroll
            for (int t = 0; t < 4; t++) O[di][t] *= corr;
        }

        // stage P: Ps[i][r]
#pragma unroll
        for (int di = 0; di < 4; di++)
            *(float4*)&Ps[(i0 + di) * 64 + j0] =
                make_float4(p[di][0], p[di][1], p[di][2], p[di][3]);
        __syncthreads();

        // ---- O += P @ V ----
#pragma unroll 8
        for (int r = 0; r < 64; r++) {
            float pa[4];
#pragma unroll
            for (int di = 0; di < 4; di++) pa[di] = Ps[(i0 + di) * 64 + r];
            float4 vf = *(const float4*)&vs[r * 64 + j0];
            float va[4] = {vf.x, vf.y, vf.z, vf.w};
#pragma unroll
            for (int di = 0; di < 4; di++)
#pragma unroll
                for (int t = 0; t < 4; t++)
                    O[di][t] += pa[di] * va[t];
        }
    }

    // epilogue: out[b][l][h*64 + dcol] = O / l
#pragma unroll
    for (int di = 0; di < 4; di++) {
        float inv = 1.f / l[di];
        int srow = l0 + i0 + di;
        float4 o4 = make_float4(O[di][0] * inv, O[di][1] * inv,
                                O[di][2] * inv, O[di][3] * inv);
        *(float4*)&out[((size_t)b * SEQ + srow) * 1024 + h * 64 + j0] = o4;
    }
}

// ---------------------------------------------------------------------------
extern "C" void kernel_launch(void* const* d_in, const int* in_sizes, int n_in,
                              void* d_out, int out_size) {
    const float* hs     = (const float*)d_in[0];  // [4,1024,1024]
    const float* qkv_w  = (const float*)d_in[1];  // [3072,1024]
    const float* qkv_b  = (const float*)d_in[2];  // [3072]
    const float* dist   = (const float*)d_in[3];  // [2047,64]
    const float* emask  = (const float*)d_in[4];  // [4,1,1,1024]
    float* out = (float*)d_out;

    dim3 g1(3072 / 128, 4096 / 128);
    qkv_gemm_kernel<<<g1, 256>>>(hs, qkv_w, qkv_b);

    const int smem_bytes = 24576 * sizeof(float);  // 98304
    cudaFuncSetAttribute(attn_kernel,
                         cudaFuncAttributeMaxDynamicSharedMemorySize, smem_bytes);
    dim3 g2(SEQ / 64, BHD);
    attn_kernel<<<g2, 256, smem_bytes>>>(dist, emask, out);
}

// round 3
// speedup vs baseline: 1.9414x; 1.9414x over previous
#include <cuda_runtime.h>
#include <cuda_bf16.h>
#include <cstdint>

#define BATCH 4
#define SEQ 1024
#define NHEADS 16
#define HDIM 64
#define BHD (BATCH*NHEADS)          // 64
#define QKV_ELEMS (BATCH*NHEADS*SEQ*HDIM)  // 4,194,304

__device__ float g_q[QKV_ELEMS];
__device__ float g_k[QKV_ELEMS];
__device__ float g_v[QKV_ELEMS];

// ---------------------------------------------------------------------------
// helpers
// ---------------------------------------------------------------------------
__device__ __forceinline__ uint32_t smem_u32(const void* p) {
    uint32_t a;
    asm("{ .reg .u64 t; cvta.to.shared.u64 t, %1; cvt.u32.u64 %0, t; }"
        : "=r"(a) : "l"(p));
    return a;
}

__device__ __forceinline__ void ldsm_x4(uint32_t* r, uint32_t addr) {
    asm volatile("ldmatrix.sync.aligned.m8n8.x4.shared.b16 {%0,%1,%2,%3}, [%4];"
                 : "=r"(r[0]), "=r"(r[1]), "=r"(r[2]), "=r"(r[3]) : "r"(addr));
}

__device__ __forceinline__ void mma16816(float* d, const uint32_t* a,
                                         uint32_t b0, uint32_t b1) {
    asm volatile(
        "mma.sync.aligned.m16n8k16.row.col.f32.bf16.bf16.f32 "
        "{%0,%1,%2,%3}, {%4,%5,%6,%7}, {%8,%9}, {%0,%1,%2,%3};"
        : "+f"(d[0]), "+f"(d[1]), "+f"(d[2]), "+f"(d[3])
        : "r"(a[0]), "r"(a[1]), "r"(a[2]), "r"(a[3]), "r"(b0), "r"(b1));
}

__device__ __forceinline__ uint32_t pack_bf16(__nv_bfloat16 a, __nv_bfloat16 b) {
    return ((uint32_t)__bfloat16_as_ushort(b) << 16) | __bfloat16_as_ushort(a);
}

// convert float4 -> 4 hi bf16 (uint2) + 4 lo bf16 (uint2)
__device__ __forceinline__ void cvt4(float4 v, uint2& hi, uint2& lo) {
    float f[4] = {v.x, v.y, v.z, v.w};
    __nv_bfloat16 h[4], l[4];
#pragma unroll
    for (int i = 0; i < 4; i++) {
        h[i] = __float2bfloat16_rn(f[i]);
        l[i] = __float2bfloat16_rn(f[i] - __bfloat162float(h[i]));
    }
    hi.x = pack_bf16(h[0], h[1]); hi.y = pack_bf16(h[2], h[3]);
    lo.x = pack_bf16(l[0], l[1]); lo.y = pack_bf16(l[2], l[3]);
}

// ---------------------------------------------------------------------------
// Kernel 1: QKV projection via mma.sync bf16x3 (hi/lo split).
// C[n,o] = sum_i A[n,i]*W[o,i] + bias[o], A=[4096,1024], W=[3072,1024].
// CTA tile 128x128, K chunks of 32, double-buffered smem + reg prefetch.
// smem per buffer: 4 planes (Ahi,Alo,Bhi,Blo), each 128 rows x 40 bf16 (80 B).
// ---------------------------------------------------------------------------
#define ASTR 40                       // bf16 elems per smem row (32 + 8 pad)
#define PLANE (128 * ASTR * 2)        // 10240 B
#define BUFSZ (4 * PLANE)             // 40960 B
#define QKV_SMEM (2 * BUFSZ)          // 81920 B

__global__ __launch_bounds__(256, 2) void qkv_mma_kernel(
    const float* __restrict__ A,
    const float* __restrict__ W,
    const float* __restrict__ bias)
{
    extern __shared__ char sm[];
    const uint32_t sbase = smem_u32(sm);
    const int tid = threadIdx.x;
    const int w = tid >> 5;
    const int lane = tid & 31;
    const int bm = blockIdx.y * 128;
    const int bn = blockIdx.x * 128;
    const int warp_m0 = (w >> 1) * 32;
    const int warp_n0 = (w & 1) * 64;

    float acc[2][8][4];
#pragma unroll
    for (int i = 0; i < 2; i++)
#pragma unroll
        for (int j = 0; j < 8; j++)
#pragma unroll
            for (int t = 0; t < 4; t++) acc[i][j][t] = 0.f;

    // global load pattern: row = tid>>1 (128 rows), 16 contiguous f32 at
    // col (tid&1)*16, i.e. 4 float4 per matrix per chunk.
    const int lrow = tid >> 1;
    const int lcol = (tid & 1) * 16;
    const float* Ap = A + (size_t)(bm + lrow) * 1024 + lcol;
    const float* Wp = W + (size_t)(bn + lrow) * 1024 + lcol;

    // smem store base (bytes within a plane)
    const int soff = lrow * (ASTR * 2) + lcol * 2;

    float4 ra[4], rb[4];
#pragma unroll
    for (int i = 0; i < 4; i++) {
        ra[i] = *(const float4*)(Ap + i * 4);
        rb[i] = *(const float4*)(Wp + i * 4);
    }

    for (int c = 0; c < 32; c++) {
        const int buf = c & 1;
        char* bp = sm + buf * BUFSZ;
        // store current chunk
#pragma unroll
        for (int i = 0; i < 4; i++) {
            uint2 hi, lo;
            cvt4(ra[i], hi, lo);
            *(uint2*)(bp + 0 * PLANE + soff + i * 8) = hi;
            *(uint2*)(bp + 1 * PLANE + soff + i * 8) = lo;
            cvt4(rb[i], hi, lo);
            *(uint2*)(bp + 2 * PLANE + soff + i * 8) = hi;
            *(uint2*)(bp + 3 * PLANE + soff + i * 8) = lo;
        }
        // prefetch next chunk
        if (c < 31) {
#pragma unroll
            for (int i = 0; i < 4; i++) {
                ra[i] = *(const float4*)(Ap + (c + 1) * 32 + i * 4);
                rb[i] = *(const float4*)(Wp + (c + 1) * 32 + i * 4);
            }
        }
        __syncthreads();

        const uint32_t bufb = sbase + buf * BUFSZ;
#pragma unroll
        for (int ks = 0; ks < 2; ks++) {
            const int kcol = ks * 16 + (lane >> 4) * 8;   // bf16 elems
            // A fragments (2 m16 tiles, hi+lo)
            uint32_t a_hi[2][4], a_lo[2][4];
#pragma unroll
            for (int mi = 0; mi < 2; mi++) {
                int arow = warp_m0 + mi * 16 + (lane & 15);
                uint32_t ad = bufb + arow * (ASTR * 2) + kcol * 2;
                ldsm_x4(a_hi[mi], ad);
                ldsm_x4(a_lo[mi], ad + PLANE);
            }
            // B: 4 tiles of 16 n-rows each
#pragma unroll
            for (int nt = 0; nt < 4; nt++) {
                uint32_t b_hi[4], b_lo[4];
                int brow = warp_n0 + nt * 16 + (lane & 15);
                uint32_t bd = bufb + 2 * PLANE + brow * (ASTR * 2) + kcol * 2;
                ldsm_x4(b_hi, bd);
                ldsm_x4(b_lo, bd + PLANE);
#pragma unroll
                for (int mi = 0; mi < 2; mi++) {
                    mma16816(acc[mi][nt * 2 + 0], a_hi[mi], b_hi[0], b_hi[2]);
                    mma16816(acc[mi][nt * 2 + 1], a_hi[mi], b_hi[1], b_hi[3]);
                    mma16816(acc[mi][nt * 2 + 0], a_hi[mi], b_lo[0], b_lo[2]);
                    mma16816(acc[mi][nt * 2 + 1], a_hi[mi], b_lo[1], b_lo[3]);
                    mma16816(acc[mi][nt * 2 + 0], a_lo[mi], b_hi[0], b_hi[2]);
                    mma16816(acc[mi][nt * 2 + 1], a_lo[mi], b_hi[1], b_hi[3]);
                }
            }
        }
        __syncthreads();
    }

    // epilogue: bias add + scatter to g_q/g_k/g_v
#pragma unroll
    for (int mi = 0; mi < 2; mi++) {
#pragma unroll
        for (int h2 = 0; h2 < 2; h2++) {
            int n = bm + warp_m0 + mi * 16 + (lane >> 2) + h2 * 8;
            int b = n >> 10;
            int s = n & 1023;
#pragma unroll
            for (int nj = 0; nj < 8; nj++) {
                int o = bn + warp_n0 + nj * 8 + (lane & 3) * 2;
                float2 bb = *(const float2*)&bias[o];
                float2 val;
                val.x = acc[mi][nj][h2 * 2 + 0] + bb.x;
                val.y = acc[mi][nj][h2 * 2 + 1] + bb.y;
                int t = o >> 10;
                int head = (o & 1023) >> 6;
                int dd = o & 63;
                float* dst = (t == 0) ? g_q : (t == 1) ? g_k : g_v;
                *(float2*)&dst[(((size_t)(b << 4) + head) << 16) | (s << 6) | dd] = val;
            }
        }
    }
}

// ---------------------------------------------------------------------------
// Kernel 2: fused attention with relative_key_query bias (fp32, unchanged).
// ---------------------------------------------------------------------------
__global__ __launch_bounds__(256, 2) void attn_kernel(
    const float* __restrict__ dist,   // [2047,64]
    const float* __restrict__ mask,   // [B,1,1,S]
    float* __restrict__ out)          // [B,S,1024]
{
    extern __shared__ float smf[];
    float* qs = smf;
    float* ks = smf + 4096;
    float* vs = smf + 8192;
    float* Ds = smf + 12288;
    float* Ps = smf + 20480;

    const int l0 = blockIdx.x * 64;
    const int bh = blockIdx.y;
    const int b  = bh >> 4;
    const int h  = bh & 15;
    const int tid = threadIdx.x;
    const int tx = tid & 15;
    const int ty = tid >> 4;
    const int i0 = ty * 4;
    const int j0 = tx * 4;
    const int dbase = i0 - j0 + 60;

    const float* qg = g_q + (size_t)bh * (SEQ * HDIM);
    const float* kg = g_k + (size_t)bh * (SEQ * HDIM);
    const float* vg = g_v + (size_t)bh * (SEQ * HDIM);

    {
        int irow = tid >> 2;
        int d0 = (tid & 3) * 16;
#pragma unroll
        for (int c = 0; c < 4; c++) {
            int d = d0 + c * 4;
            float4 q4 = *(const float4*)&qg[(l0 + irow) * 64 + d];
            qs[(d + 0) * 64 + irow] = q4.x;
            qs[(d + 1) * 64 + irow] = q4.y;
            qs[(d + 2) * 64 + irow] = q4.z;
            qs[(d + 3) * 64 + irow] = q4.w;
        }
    }

    float O[4][4];
    float m[4], l[4];
#pragma unroll
    for (int i = 0; i < 4; i++) {
        m[i] = -1e30f; l[i] = 0.f;
#pragma unroll
        for (int j = 0; j < 4; j++) O[i][j] = 0.f;
    }

    for (int r0 = 0; r0 < SEQ; r0 += 64) {
        __syncthreads();
        {
            int jrow = tid >> 2;
            int d0 = (tid & 3) * 16;
#pragma unroll
            for (int c = 0; c < 4; c++) {
                int d = d0 + c * 4;
                float4 k4 = *(const float4*)&kg[(r0 + jrow) * 64 + d];
                ks[(d + 0) * 64 + jrow] = k4.x;
                ks[(d + 1) * 64 + jrow] = k4.y;
                ks[(d + 2) * 64 + jrow] = k4.z;
                ks[(d + 3) * 64 + jrow] = k4.w;
                float4 v4 = *(const float4*)&vg[(r0 + jrow) * 64 + d];
                *(float4*)&vs[jrow * 64 + d] = v4;
            }
            int jb = l0 - r0 + 960;
#pragma unroll
            for (int it = 0; it < 2; it++) {
                int delta = (tid >> 2) + it * 64;
                if (delta < 127) {
                    int dd0 = (tid & 3) * 16;
#pragma unroll
                    for (int c = 0; c < 4; c++) {
                        int d = dd0 + c * 4;
                        float4 p4 = *(const float4*)&dist[(jb + delta) * 64 + d];
                        Ds[(d + 0) * 128 + delta] = p4.x;
                        Ds[(d + 1) * 128 + delta] = p4.y;
                        Ds[(d + 2) * 128 + delta] = p4.z;
                        Ds[(d + 3) * 128 + delta] = p4.w;
                    }
                }
            }
        }
        __syncthreads();

        float acc[4][4];
#pragma unroll
        for (int i = 0; i < 4; i++)
#pragma unroll
            for (int j = 0; j < 4; j++) acc[i][j] = 0.f;

#pragma unroll 8
        for (int d = 0; d < 64; d++) {
            float4 qf = *(const float4*)&qs[d * 64 + i0];
            float4 kf = *(const float4*)&ks[d * 64 + j0];
            float4 d0f = *(const float4*)&Ds[d * 128 + dbase];
            float4 d1f = *(const float4*)&Ds[d * 128 + dbase + 4];
            float qa[4] = {qf.x, qf.y, qf.z, qf.w};
            float ka[4] = {kf.x, kf.y, kf.z, kf.w};
            float da[8] = {d0f.x, d0f.y, d0f.z, d0f.w, d1f.x, d1f.y, d1f.z, d1f.w};
#pragma unroll
            for (int di = 0; di < 4; di++)
#pragma unroll
                for (int dj = 0; dj < 4; dj++) {
                    float dv = da[di - dj + 3];
                    acc[di][dj] += qa[di] * (ka[dj] + dv) + ka[dj] * dv;
                }
        }

        float4 mk4 = *(const float4*)&mask[b * SEQ + r0 + j0];
        float mk[4] = {mk4.x, mk4.y, mk4.z, mk4.w};
        float p[4][4];
#pragma unroll
        for (int di = 0; di < 4; di++) {
            float s_[4];
#pragma unroll
            for (int dj = 0; dj < 4; dj++)
                s_[dj] = acc[di][dj] * 0.125f + mk[dj];
            float rmax = fmaxf(fmaxf(s_[0], s_[1]), fmaxf(s_[2], s_[3]));
#pragma unroll
            for (int off = 1; off < 16; off <<= 1)
                rmax = fmaxf(rmax, __shfl_xor_sync(0xffffffffu, rmax, off));
            float mnew = fmaxf(m[di], rmax);
            float corr = __expf(m[di] - mnew);
            float rsum = 0.f;
#pragma unroll
            for (int dj = 0; dj < 4; dj++) {
                p[di][dj] = __expf(s_[dj] - mnew);
                rsum += p[di][dj];
            }
#pragma unroll
            for (int off = 1; off < 16; off <<= 1)
                rsum += __shfl_xor_sync(0xffffffffu, rsum, off);
            l[di] = l[di] * corr + rsum;
            m[di] = mnew;
#pragma unroll
            for (int t = 0; t < 4; t++) O[di][t] *= corr;
        }

#pragma unroll
        for (int di = 0; di < 4; di++)
            *(float4*)&Ps[(i0 + di) * 64 + j0] =
                make_float4(p[di][0], p[di][1], p[di][2], p[di][3]);
        __syncthreads();

#pragma unroll 8
        for (int r = 0; r < 64; r++) {
            float pa[4];
#pragma unroll
            for (int di = 0; di < 4; di++) pa[di] = Ps[(i0 + di) * 64 + r];
            float4 vf = *(const float4*)&vs[r * 64 + j0];
            float va[4] = {vf.x, vf.y, vf.z, vf.w};
#pragma unroll
            for (int di = 0; di < 4; di++)
#pragma unroll
                for (int t = 0; t < 4; t++)
                    O[di][t] += pa[di] * va[t];
        }
    }

#pragma unroll
    for (int di = 0; di < 4; di++) {
        float inv = 1.f / l[di];
        int srow = l0 + i0 + di;
        float4 o4 = make_float4(O[di][0] * inv, O[di][1] * inv,
                                O[di][2] * inv, O[di][3] * inv);
        *(float4*)&out[((size_t)b * SEQ + srow) * 1024 + h * 64 + j0] = o4;
    }
}

// ---------------------------------------------------------------------------
extern "C" void kernel_launch(void* const* d_in, const int* in_sizes, int n_in,
                              void* d_out, int out_size) {
    const float* hs     = (const float*)d_in[0];  // [4,1024,1024]
    const float* qkv_w  = (const float*)d_in[1];  // [3072,1024]
    const float* qkv_b  = (const float*)d_in[2];  // [3072]
    const float* dist   = (const float*)d_in[3];  // [2047,64]
    const float* emask  = (const float*)d_in[4];  // [4,1,1,1024]
    float* out = (float*)d_out;

    cudaFuncSetAttribute(qkv_mma_kernel,
                         cudaFuncAttributeMaxDynamicSharedMemorySize, QKV_SMEM);
    dim3 g1(3072 / 128, 4096 / 128);
    qkv_mma_kernel<<<g1, 256, QKV_SMEM>>>(hs, qkv_w, qkv_b);

    const int smem_bytes = 24576 * sizeof(float);  // 98304
    cudaFuncSetAttribute(attn_kernel,
                         cudaFuncAttributeMaxDynamicSharedMemorySize, smem_bytes);
    dim3 g2(SEQ / 64, BHD);
    attn_kernel<<<g2, 256, smem_bytes>>>(dist, emask, out);
}

// round 7
// speedup vs baseline: 2.5585x; 1.3179x over previous
#include <cuda_runtime.h>
#include <cuda_bf16.h>
#include <cstdint>

#define BATCH 4
#define SEQ 1024
#define NHEADS 16
#define HDIM 64
#define BHD (BATCH*NHEADS)          // 64
#define QKV_ELEMS (BATCH*NHEADS*SEQ*HDIM)  // 4,194,304

__device__ float g_q[QKV_ELEMS];
__device__ float g_k[QKV_ELEMS];
__device__ float g_v[QKV_ELEMS];

// ---------------------------------------------------------------------------
// helpers
// ---------------------------------------------------------------------------
__device__ __forceinline__ uint32_t smem_u32(const void* p) {
    uint32_t a;
    asm("{ .reg .u64 t; cvta.to.shared.u64 t, %1; cvt.u32.u64 %0, t; }"
        : "=r"(a) : "l"(p));
    return a;
}

__device__ __forceinline__ void ldsm_x4(uint32_t* r, uint32_t addr) {
    asm volatile("ldmatrix.sync.aligned.m8n8.x4.shared.b16 {%0,%1,%2,%3}, [%4];"
                 : "=r"(r[0]), "=r"(r[1]), "=r"(r[2]), "=r"(r[3]) : "r"(addr));
}

__device__ __forceinline__ void ldsm_x4_t(uint32_t* r, uint32_t addr) {
    asm volatile("ldmatrix.sync.aligned.m8n8.x4.trans.shared.b16 {%0,%1,%2,%3}, [%4];"
                 : "=r"(r[0]), "=r"(r[1]), "=r"(r[2]), "=r"(r[3]) : "r"(addr));
}

__device__ __forceinline__ void mma16816(float* d, const uint32_t* a,
                                         uint32_t b0, uint32_t b1) {
    asm volatile(
        "mma.sync.aligned.m16n8k16.row.col.f32.bf16.bf16.f32 "
        "{%0,%1,%2,%3}, {%4,%5,%6,%7}, {%8,%9}, {%0,%1,%2,%3};"
        : "+f"(d[0]), "+f"(d[1]), "+f"(d[2]), "+f"(d[3])
        : "r"(a[0]), "r"(a[1]), "r"(a[2]), "r"(a[3]), "r"(b0), "r"(b1));
}

__device__ __forceinline__ uint32_t pack_bf16(__nv_bfloat16 a, __nv_bfloat16 b) {
    return ((uint32_t)__bfloat16_as_ushort(b) << 16) | __bfloat16_as_ushort(a);
}

__device__ __forceinline__ void cvt4(float4 v, uint2& hi, uint2& lo) {
    float f[4] = {v.x, v.y, v.z, v.w};
    __nv_bfloat16 h[4], l[4];
#pragma unroll
    for (int i = 0; i < 4; i++) {
        h[i] = __float2bfloat16_rn(f[i]);
        l[i] = __float2bfloat16_rn(f[i] - __bfloat162float(h[i]));
    }
    hi.x = pack_bf16(h[0], h[1]); hi.y = pack_bf16(h[2], h[3]);
    lo.x = pack_bf16(l[0], l[1]); lo.y = pack_bf16(l[2], l[3]);
}

__device__ __forceinline__ uint2 cvt4h(float4 v) {
    uint2 hi;
    hi.x = pack_bf16(__float2bfloat16_rn(v.x), __float2bfloat16_rn(v.y));
    hi.y = pack_bf16(__float2bfloat16_rn(v.z), __float2bfloat16_rn(v.w));
    return hi;
}

// ---------------------------------------------------------------------------
// Kernel 1: QKV projection via mma.sync bf16x3 (unchanged from R3).
// ---------------------------------------------------------------------------
#define ASTR 40
#define PLANE (128 * ASTR * 2)
#define BUFSZ (4 * PLANE)
#define QKV_SMEM (2 * BUFSZ)

__global__ __launch_bounds__(256, 2) void qkv_mma_kernel(
    const float* __restrict__ A,
    const float* __restrict__ W,
    const float* __restrict__ bias)
{
    extern __shared__ char sm[];
    const uint32_t sbase = smem_u32(sm);
    const int tid = threadIdx.x;
    const int w = tid >> 5;
    const int lane = tid & 31;
    const int bm = blockIdx.y * 128;
    const int bn = blockIdx.x * 128;
    const int warp_m0 = (w >> 1) * 32;
    const int warp_n0 = (w & 1) * 64;

    float acc[2][8][4];
#pragma unroll
    for (int i = 0; i < 2; i++)
#pragma unroll
        for (int j = 0; j < 8; j++)
#pragma unroll
            for (int t = 0; t < 4; t++) acc[i][j][t] = 0.f;

    const int lrow = tid >> 1;
    const int lcol = (tid & 1) * 16;
    const float* Ap = A + (size_t)(bm + lrow) * 1024 + lcol;
    const float* Wp = W + (size_t)(bn + lrow) * 1024 + lcol;
    const int soff = lrow * (ASTR * 2) + lcol * 2;

    float4 ra[4], rb[4];
#pragma unroll
    for (int i = 0; i < 4; i++) {
        ra[i] = *(const float4*)(Ap + i * 4);
        rb[i] = *(const float4*)(Wp + i * 4);
    }

    for (int c = 0; c < 32; c++) {
        const int buf = c & 1;
        char* bp = sm + buf * BUFSZ;
#pragma unroll
        for (int i = 0; i < 4; i++) {
            uint2 hi, lo;
            cvt4(ra[i], hi, lo);
            *(uint2*)(bp + 0 * PLANE + soff + i * 8) = hi;
            *(uint2*)(bp + 1 * PLANE + soff + i * 8) = lo;
            cvt4(rb[i], hi, lo);
            *(uint2*)(bp + 2 * PLANE + soff + i * 8) = hi;
            *(uint2*)(bp + 3 * PLANE + soff + i * 8) = lo;
        }
        if (c < 31) {
#pragma unroll
            for (int i = 0; i < 4; i++) {
                ra[i] = *(const float4*)(Ap + (c + 1) * 32 + i * 4);
                rb[i] = *(const float4*)(Wp + (c + 1) * 32 + i * 4);
            }
        }
        __syncthreads();

        const uint32_t bufb = sbase + buf * BUFSZ;
#pragma unroll
        for (int ks = 0; ks < 2; ks++) {
            const int kcol = ks * 16 + (lane >> 4) * 8;
            uint32_t a_hi[2][4], a_lo[2][4];
#pragma unroll
            for (int mi = 0; mi < 2; mi++) {
                int arow = warp_m0 + mi * 16 + (lane & 15);
                uint32_t ad = bufb + arow * (ASTR * 2) + kcol * 2;
                ldsm_x4(a_hi[mi], ad);
                ldsm_x4(a_lo[mi], ad + PLANE);
            }
#pragma unroll
            for (int nt = 0; nt < 4; nt++) {
                uint32_t b_hi[4], b_lo[4];
                int brow = warp_n0 + nt * 16 + (lane & 15);
                uint32_t bd = bufb + 2 * PLANE + brow * (ASTR * 2) + kcol * 2;
                ldsm_x4(b_hi, bd);
                ldsm_x4(b_lo, bd + PLANE);
#pragma unroll
                for (int mi = 0; mi < 2; mi++) {
                    mma16816(acc[mi][nt * 2 + 0], a_hi[mi], b_hi[0], b_hi[2]);
                    mma16816(acc[mi][nt * 2 + 1], a_hi[mi], b_hi[1], b_hi[3]);
                    mma16816(acc[mi][nt * 2 + 0], a_hi[mi], b_lo[0], b_lo[2]);
                    mma16816(acc[mi][nt * 2 + 1], a_hi[mi], b_lo[1], b_lo[3]);
                    mma16816(acc[mi][nt * 2 + 0], a_lo[mi], b_hi[0], b_hi[2]);
                    mma16816(acc[mi][nt * 2 + 1], a_lo[mi], b_hi[1], b_hi[3]);
                }
            }
        }
        __syncthreads();
    }

#pragma unroll
    for (int mi = 0; mi < 2; mi++) {
#pragma unroll
        for (int h2 = 0; h2 < 2; h2++) {
            int n = bm + warp_m0 + mi * 16 + (lane >> 2) + h2 * 8;
            int b = n >> 10;
            int s = n & 1023;
#pragma unroll
            for (int nj = 0; nj < 8; nj++) {
                int o = bn + warp_n0 + nj * 8 + (lane & 3) * 2;
                float2 bb = *(const float2*)&bias[o];
                float2 val;
                val.x = acc[mi][nj][h2 * 2 + 0] + bb.x;
                val.y = acc[mi][nj][h2 * 2 + 1] + bb.y;
                int t = o >> 10;
                int head = (o & 1023) >> 6;
                int dd = o & 63;
                float* dst = (t == 0) ? g_q : (t == 1) ? g_k : g_v;
                *(float2*)&dst[(((size_t)(b << 4) + head) << 16) | (s << 6) | dd] = val;
            }
        }
    }
}

// ---------------------------------------------------------------------------
// Kernel 2: tensor-core fused attention with relative_key_query bias.
// CTA = (l-tile of 64 rows, bh). 256 threads, 8 warps (4 wm x 2 wn).
// scores = QK (bf16 hi/lo 3-pass) + gather(QD) + gather(KD), online softmax,
// O += P(hi/lo) @ V(hi/lo) (3-pass).
// ---------------------------------------------------------------------------
#define TST 144                    // byte stride for 72-bf16 rows
#define OFF_QHI 0
#define OFF_QLO 9216
#define OFF_KHI 18432
#define OFF_KLO 27648
#define OFF_VHI 36864
#define OFF_VLO 46080
#define OFF_D   55296              // 128 rows x TST = 18432
#define OFF_QD  73728              // 64 x 260 B
#define OFF_KD  90368
#define OFF_PHI 107008
#define OFF_PLO 116224
#define OFF_RMAX 125440            // [2][64] f32
#define OFF_RSUM 125952            // [2][64] f32
#define OFF_MASK 126464            // [64] f32
#define ATTN_SMEM 126720
#define QDSTR 260                  // byte stride for QD/KD rows (130 bf16)

__global__ __launch_bounds__(256, 1) void attn_mma_kernel(
    const float* __restrict__ dist,   // [2047,64]
    const float* __restrict__ mask,   // [B,1,1,S]
    float* __restrict__ out)          // [B,S,1024]
{
    extern __shared__ char sm[];
    const uint32_t sb = smem_u32(sm);
    const int tid = threadIdx.x;
    const int w = tid >> 5;
    const int lane = tid & 31;
    const int wm = w >> 1;            // 0..3 -> rows 16*wm
    const int wn = w & 1;             // 0..1 -> cols 32*wn
    const int l0g = blockIdx.x * 64;
    const int bh = blockIdx.y;
    const int b = bh >> 4;
    const int h = bh & 15;

    const float* qg = g_q + (size_t)bh * (SEQ * HDIM);
    const float* kg = g_k + (size_t)bh * (SEQ * HDIM);
    const float* vg = g_v + (size_t)bh * (SEQ * HDIM);

    // ---- load Q tile (once): rows l0g..+63, hi/lo bf16 ----
    {
        const int row = tid >> 2;
        const int c0 = (tid & 3) * 16;
        const float* src = qg + (l0g + row) * 64 + c0;
        char* dhi = sm + OFF_QHI + row * TST + c0 * 2;
        char* dlo = sm + OFF_QLO + row * TST + c0 * 2;
#pragma unroll
        for (int i = 0; i < 4; i++) {
            uint2 hi, lo;
            cvt4(*(const float4*)(src + i * 4), hi, lo);
            *(uint2*)(dhi + i * 8) = hi;
            *(uint2*)(dlo + i * 8) = lo;
        }
    }

    float O[4][4];
#pragma unroll
    for (int i = 0; i < 4; i++)
#pragma unroll
        for (int j = 0; j < 4; j++) O[i][j] = 0.f;
    float m0r = -1e30f, m1r = -1e30f, l0r = 0.f, l1r = 0.f;

    const int lr0 = 16 * wm + (lane >> 2);
    const int lr1 = lr0 + 8;

    for (int r0 = 0; r0 < SEQ; r0 += 64) {
        __syncthreads();  // also protects Q load on first iter / prev-iter reads
        // ---- load K (hi/lo), V (hi/lo), D band (bf16), mask ----
        {
            const int row = tid >> 2;
            const int c0 = (tid & 3) * 16;
            const float* ks = kg + (r0 + row) * 64 + c0;
            const float* vs = vg + (r0 + row) * 64 + c0;
            char* dkh = sm + OFF_KHI + row * TST + c0 * 2;
            char* dkl = sm + OFF_KLO + row * TST + c0 * 2;
            char* dvh = sm + OFF_VHI + row * TST + c0 * 2;
            char* dvl = sm + OFF_VLO + row * TST + c0 * 2;
#pragma unroll
            for (int i = 0; i < 4; i++) {
                uint2 hi, lo;
                cvt4(*(const float4*)(ks + i * 4), hi, lo);
                *(uint2*)(dkh + i * 8) = hi;
                *(uint2*)(dkl + i * 8) = lo;
                cvt4(*(const float4*)(vs + i * 4), hi, lo);
                *(uint2*)(dvh + i * 8) = hi;
                *(uint2*)(dvl + i * 8) = lo;
            }
            // D band: Dband[j] = dist[jb + j], j in [0,127)
            const int jb = l0g - r0 + 960;
            const int drow = tid >> 1;
            const int dc0 = (tid & 1) * 32;
            char* dd = sm + OFF_D + drow * TST + dc0 * 2;
            if (drow < 127) {
                const float* dsrc = dist + (size_t)(jb + drow) * 64 + dc0;
#pragma unroll
                for (int i = 0; i < 8; i++)
                    *(uint2*)(dd + i * 8) = cvt4h(*(const float4*)(dsrc + i * 4));
            } else {
#pragma unroll
                for (int i = 0; i < 8; i++)
                    *(uint2*)(dd + i * 8) = make_uint2(0u, 0u);
            }
            if (tid < 64)
                *(float*)(sm + OFF_MASK + tid * 4) = mask[b * SEQ + r0 + tid];
        }
        __syncthreads();

        // ---- QK scores (hi/lo 3 passes): warp tile 16 x 32 ----
        float accs[4][4];
#pragma unroll
        for (int i = 0; i < 4; i++)
#pragma unroll
            for (int j = 0; j < 4; j++) accs[i][j] = 0.f;

#pragma unroll
        for (int k = 0; k < 4; k++) {
            const int kc = (k * 16 + (lane >> 4) * 8) * 2;
            uint32_t a_hi[4], a_lo[4];
            uint32_t arow = sb + (16 * wm + (lane & 15)) * TST + kc;
            ldsm_x4(a_hi, arow + OFF_QHI);
            ldsm_x4(a_lo, arow + OFF_QLO);
#pragma unroll
            for (int np = 0; np < 2; np++) {
                uint32_t bh4[4], bl4[4];
                uint32_t brow = sb + (32 * wn + 16 * np + (lane & 15)) * TST + kc;
                ldsm_x4(bh4, brow + OFF_KHI);
                ldsm_x4(bl4, brow + OFF_KLO);
                mma16816(accs[2 * np + 0], a_hi, bh4[0], bh4[2]);
                mma16816(accs[2 * np + 1], a_hi, bh4[1], bh4[3]);
                mma16816(accs[2 * np + 0], a_hi, bl4[0], bl4[2]);
                mma16816(accs[2 * np + 1], a_hi, bl4[1], bl4[3]);
                mma16816(accs[2 * np + 0], a_lo, bh4[0], bh4[2]);
                mma16816(accs[2 * np + 1], a_lo, bh4[1], bh4[3]);
            }
        }

        // ---- QD then KD (single bf16 pass): warp tile 16 x 64 ----
        float acc2[8][4];
#pragma unroll
        for (int pass = 0; pass < 2; pass++) {
            const uint32_t aoff = (pass == 0) ? OFF_QHI : OFF_KHI;
            const uint32_t ooff = (pass == 0) ? OFF_QD : OFF_KD;
#pragma unroll
            for (int i = 0; i < 8; i++)
#pragma unroll
                for (int j = 0; j < 4; j++) acc2[i][j] = 0.f;
#pragma unroll
            for (int k = 0; k < 4; k++) {
                const int kc = (k * 16 + (lane >> 4) * 8) * 2;
                uint32_t a4[4];
                ldsm_x4(a4, sb + aoff + (16 * wm + (lane & 15)) * TST + kc);
#pragma unroll
                for (int np = 0; np < 4; np++) {
                    uint32_t b4[4];
                    ldsm_x4(b4, sb + OFF_D + (64 * wn + 16 * np + (lane & 15)) * TST + kc);
                    mma16816(acc2[2 * np + 0], a4, b4[0], b4[2]);
                    mma16816(acc2[2 * np + 1], a4, b4[1], b4[3]);
                }
            }
            // store to QDs/KDs as bf16
#pragma unroll
            for (int nt = 0; nt < 8; nt++) {
                const int col = 64 * wn + 8 * nt + 2 * (lane & 3);
                *(uint32_t*)(sm + ooff + lr0 * QDSTR + col * 2) =
                    pack_bf16(__float2bfloat16_rn(acc2[nt][0]),
                              __float2bfloat16_rn(acc2[nt][1]));
                *(uint32_t*)(sm + ooff + lr1 * QDSTR + col * 2) =
                    pack_bf16(__float2bfloat16_rn(acc2[nt][2]),
                              __float2bfloat16_rn(acc2[nt][3]));
            }
        }
        __syncthreads();

        // ---- gather + scale + mask ----
        const __nv_bfloat16* QDp = (const __nv_bfloat16*)(sm + OFF_QD);
        const __nv_bfloat16* KDp = (const __nv_bfloat16*)(sm + OFF_KD);
        const float* msk = (const float*)(sm + OFF_MASK);
#pragma unroll
        for (int nt = 0; nt < 4; nt++) {
            const int c = 32 * wn + 8 * nt + 2 * (lane & 3);
#pragma unroll
            for (int e = 0; e < 4; e++) {
                const int row = (e < 2) ? lr0 : lr1;
                const int col = c + (e & 1);
                const int j = row - col + 63;
                float v = accs[nt][e]
                        + __bfloat162float(QDp[row * 130 + j])
                        + __bfloat162float(KDp[col * 130 + j]);
                accs[nt][e] = v * 0.125f + msk[col];
            }
        }

        // ---- online softmax ----
        float vmax0 = -1e30f, vmax1 = -1e30f;
#pragma unroll
        for (int nt = 0; nt < 4; nt++) {
            vmax0 = fmaxf(vmax0, fmaxf(accs[nt][0], accs[nt][1]));
            vmax1 = fmaxf(vmax1, fmaxf(accs[nt][2], accs[nt][3]));
        }
#pragma unroll
        for (int off = 1; off < 4; off <<= 1) {
            vmax0 = fmaxf(vmax0, __shfl_xor_sync(0xffffffffu, vmax0, off));
            vmax1 = fmaxf(vmax1, __shfl_xor_sync(0xffffffffu, vmax1, off));
        }
        float* rmax = (float*)(sm + OFF_RMAX);
        if ((lane & 3) == 0) {
            rmax[wn * 64 + lr0] = vmax0;
            rmax[wn * 64 + lr1] = vmax1;
        }
        __syncthreads();
        const float mn0 = fmaxf(m0r, fmaxf(rmax[lr0], rmax[64 + lr0]));
        const float mn1 = fmaxf(m1r, fmaxf(rmax[lr1], rmax[64 + lr1]));
        const float corr0 = __expf(m0r - mn0);
        const float corr1 = __expf(m1r - mn1);
        m0r = mn0; m1r = mn1;

        float vsum0 = 0.f, vsum1 = 0.f;
#pragma unroll
        for (int nt = 0; nt < 4; nt++) {
            accs[nt][0] = __expf(accs[nt][0] - mn0);
            accs[nt][1] = __expf(accs[nt][1] - mn0);
            accs[nt][2] = __expf(accs[nt][2] - mn1);
            accs[nt][3] = __expf(accs[nt][3] - mn1);
            vsum0 += accs[nt][0] + accs[nt][1];
            vsum1 += accs[nt][2] + accs[nt][3];
        }
#pragma unroll
        for (int off = 1; off < 4; off <<= 1) {
            vsum0 += __shfl_xor_sync(0xffffffffu, vsum0, off);
            vsum1 += __shfl_xor_sync(0xffffffffu, vsum1, off);
        }
        float* rsum = (float*)(sm + OFF_RSUM);
        if ((lane & 3) == 0) {
            rsum[wn * 64 + lr0] = vsum0;
            rsum[wn * 64 + lr1] = vsum1;
        }
        // stage P hi/lo
#pragma unroll
        for (int nt = 0; nt < 4; nt++) {
            const int col = 32 * wn + 8 * nt + 2 * (lane & 3);
            __nv_bfloat16 h0 = __float2bfloat16_rn(accs[nt][0]);
            __nv_bfloat16 h1 = __float2bfloat16_rn(accs[nt][1]);
            __nv_bfloat16 h2 = __float2bfloat16_rn(accs[nt][2]);
            __nv_bfloat16 h3 = __float2bfloat16_rn(accs[nt][3]);
            *(uint32_t*)(sm + OFF_PHI + lr0 * TST + col * 2) = pack_bf16(h0, h1);
            *(uint32_t*)(sm + OFF_PHI + lr1 * TST + col * 2) = pack_bf16(h2, h3);
            *(uint32_t*)(sm + OFF_PLO + lr0 * TST + col * 2) = pack_bf16(
                __float2bfloat16_rn(accs[nt][0] - __bfloat162float(h0)),
                __float2bfloat16_rn(accs[nt][1] - __bfloat162float(h1)));
            *(uint32_t*)(sm + OFF_PLO + lr1 * TST + col * 2) = pack_bf16(
                __float2bfloat16_rn(accs[nt][2] - __bfloat162float(h2)),
                __float2bfloat16_rn(accs[nt][3] - __bfloat162float(h3)));
        }
        // rescale O
#pragma unroll
        for (int nt = 0; nt < 4; nt++) {
            O[nt][0] *= corr0; O[nt][1] *= corr0;
            O[nt][2] *= corr1; O[nt][3] *= corr1;
        }
        __syncthreads();
        l0r = l0r * corr0 + rsum[lr0] + rsum[64 + lr0];
        l1r = l1r * corr1 + rsum[lr1] + rsum[64 + lr1];

        // ---- O += P @ V (hi/lo x hi/lo, 3 passes) ----
#pragma unroll
        for (int k = 0; k < 4; k++) {
            const int kc = (k * 16 + (lane >> 4) * 8) * 2;
            uint32_t a_hi[4], a_lo[4];
            uint32_t arow = sb + (16 * wm + (lane & 15)) * TST + kc;
            ldsm_x4(a_hi, arow + OFF_PHI);
            ldsm_x4(a_lo, arow + OFF_PLO);
#pragma unroll
            for (int np = 0; np < 2; np++) {
                uint32_t bth[4], btl[4];
                const uint32_t vaddr = sb + (k * 16 + (lane & 15)) * TST
                              + (32 * wn + 16 * np + (lane >> 4) * 8) * 2;
                ldsm_x4_t(bth, vaddr + OFF_VHI);
                ldsm_x4_t(btl, vaddr + OFF_VLO);
                mma16816(O[2 * np + 0], a_hi, bth[0], bth[1]);
                mma16816(O[2 * np + 1], a_hi, bth[2], bth[3]);
                mma16816(O[2 * np + 0], a_hi, btl[0], btl[1]);
                mma16816(O[2 * np + 1], a_hi, btl[2], btl[3]);
                mma16816(O[2 * np + 0], a_lo, bth[0], bth[1]);
                mma16816(O[2 * np + 1], a_lo, bth[2], bth[3]);
            }
        }
    }

    // ---- epilogue ----
    const float inv0 = 1.f / l0r;
    const float inv1 = 1.f / l1r;
#pragma unroll
    for (int nt = 0; nt < 4; nt++) {
        const int dcol = 32 * wn + 8 * nt + 2 * (lane & 3);
        float2 o0 = make_float2(O[nt][0] * inv0, O[nt][1] * inv0);
        float2 o1 = make_float2(O[nt][2] * inv1, O[nt][3] * inv1);
        *(float2*)&out[((size_t)(b * SEQ) + l0g + lr0) * 1024 + h * 64 + dcol] = o0;
        *(float2*)&out[((size_t)(b * SEQ) + l0g + lr1) * 1024 + h * 64 + dcol] = o1;
    }
}

// ---------------------------------------------------------------------------
extern "C" void kernel_launch(void* const* d_in, const int* in_sizes, int n_in,
                              void* d_out, int out_size) {
    const float* hs     = (const float*)d_in[0];  // [4,1024,1024]
    const float* qkv_w  = (const float*)d_in[1];  // [3072,1024]
    const float* qkv_b  = (const float*)d_in[2];  // [3072]
    const float* dist   = (const float*)d_in[3];  // [2047,64]
    const float* emask  = (const float*)d_in[4];  // [4,1,1,1024]
    float* out = (float*)d_out;

    cudaFuncSetAttribute(qkv_mma_kernel,
                         cudaFuncAttributeMaxDynamicSharedMemorySize, QKV_SMEM);
    dim3 g1(3072 / 128, 4096 / 128);
    qkv_mma_kernel<<<g1, 256, QKV_SMEM>>>(hs, qkv_w, qkv_b);

    cudaFuncSetAttribute(attn_mma_kernel,
                         cudaFuncAttributeMaxDynamicSharedMemorySize, ATTN_SMEM);
    dim3 g2(SEQ / 64, BHD);
    attn_mma_kernel<<<g2, 256, ATTN_SMEM>>>(dist, emask, out);
}

// round 9
// speedup vs baseline: 2.7276x; 1.0661x over previous
#include <cuda_runtime.h>
#include <cuda_bf16.h>
#include <cstdint>

#define BATCH 4
#define SEQ 1024
#define NHEADS 16
#define HDIM 64
#define BHD (BATCH*NHEADS)          // 64
#define QKV_ELEMS (BATCH*NHEADS*SEQ*HDIM)  // 4,194,304

__device__ float g_q[QKV_ELEMS];
__device__ float g_k[QKV_ELEMS];
__device__ float g_v[QKV_ELEMS];

// ---------------------------------------------------------------------------
// helpers
// ---------------------------------------------------------------------------
__device__ __forceinline__ uint32_t smem_u32(const void* p) {
    uint32_t a;
    asm("{ .reg .u64 t; cvta.to.shared.u64 t, %1; cvt.u32.u64 %0, t; }"
        : "=r"(a) : "l"(p));
    return a;
}

__device__ __forceinline__ void ldsm_x4(uint32_t* r, uint32_t addr) {
    asm volatile("ldmatrix.sync.aligned.m8n8.x4.shared.b16 {%0,%1,%2,%3}, [%4];"
                 : "=r"(r[0]), "=r"(r[1]), "=r"(r[2]), "=r"(r[3]) : "r"(addr));
}

__device__ __forceinline__ void ldsm_x4_t(uint32_t* r, uint32_t addr) {
    asm volatile("ldmatrix.sync.aligned.m8n8.x4.trans.shared.b16 {%0,%1,%2,%3}, [%4];"
                 : "=r"(r[0]), "=r"(r[1]), "=r"(r[2]), "=r"(r[3]) : "r"(addr));
}

__device__ __forceinline__ void mma16816(float* d, const uint32_t* a,
                                         uint32_t b0, uint32_t b1) {
    asm volatile(
        "mma.sync.aligned.m16n8k16.row.col.f32.bf16.bf16.f32 "
        "{%0,%1,%2,%3}, {%4,%5,%6,%7}, {%8,%9}, {%0,%1,%2,%3};"
        : "+f"(d[0]), "+f"(d[1]), "+f"(d[2]), "+f"(d[3])
        : "r"(a[0]), "r"(a[1]), "r"(a[2]), "r"(a[3]), "r"(b0), "r"(b1));
}

__device__ __forceinline__ uint32_t pack_bf16(__nv_bfloat16 a, __nv_bfloat16 b) {
    return ((uint32_t)__bfloat16_as_ushort(b) << 16) | __bfloat16_as_ushort(a);
}

__device__ __forceinline__ void cvt4(float4 v, uint2& hi, uint2& lo) {
    float f[4] = {v.x, v.y, v.z, v.w};
    __nv_bfloat16 h[4], l[4];
#pragma unroll
    for (int i = 0; i < 4; i++) {
        h[i] = __float2bfloat16_rn(f[i]);
        l[i] = __float2bfloat16_rn(f[i] - __bfloat162float(h[i]));
    }
    hi.x = pack_bf16(h[0], h[1]); hi.y = pack_bf16(h[2], h[3]);
    lo.x = pack_bf16(l[0], l[1]); lo.y = pack_bf16(l[2], l[3]);
}

__device__ __forceinline__ uint2 cvt4h(float4 v) {
    uint2 hi;
    hi.x = pack_bf16(__float2bfloat16_rn(v.x), __float2bfloat16_rn(v.y));
    hi.y = pack_bf16(__float2bfloat16_rn(v.z), __float2bfloat16_rn(v.w));
    return hi;
}

// ---------------------------------------------------------------------------
// Kernel 1: QKV projection via mma.sync bf16x3 (unchanged).
// ---------------------------------------------------------------------------
#define ASTR 40
#define PLANE (128 * ASTR * 2)
#define BUFSZ (4 * PLANE)
#define QKV_SMEM (2 * BUFSZ)

__global__ __launch_bounds__(256, 2) void qkv_mma_kernel(
    const float* __restrict__ A,
    const float* __restrict__ W,
    const float* __restrict__ bias)
{
    extern __shared__ char sm[];
    const uint32_t sbase = smem_u32(sm);
    const int tid = threadIdx.x;
    const int w = tid >> 5;
    const int lane = tid & 31;
    const int bm = blockIdx.y * 128;
    const int bn = blockIdx.x * 128;
    const int warp_m0 = (w >> 1) * 32;
    const int warp_n0 = (w & 1) * 64;

    float acc[2][8][4];
#pragma unroll
    for (int i = 0; i < 2; i++)
#pragma unroll
        for (int j = 0; j < 8; j++)
#pragma unroll
            for (int t = 0; t < 4; t++) acc[i][j][t] = 0.f;

    const int lrow = tid >> 1;
    const int lcol = (tid & 1) * 16;
    const float* Ap = A + (size_t)(bm + lrow) * 1024 + lcol;
    const float* Wp = W + (size_t)(bn + lrow) * 1024 + lcol;
    const int soff = lrow * (ASTR * 2) + lcol * 2;

    float4 ra[4], rb[4];
#pragma unroll
    for (int i = 0; i < 4; i++) {
        ra[i] = *(const float4*)(Ap + i * 4);
        rb[i] = *(const float4*)(Wp + i * 4);
    }

    for (int c = 0; c < 32; c++) {
        const int buf = c & 1;
        char* bp = sm + buf * BUFSZ;
#pragma unroll
        for (int i = 0; i < 4; i++) {
            uint2 hi, lo;
            cvt4(ra[i], hi, lo);
            *(uint2*)(bp + 0 * PLANE + soff + i * 8) = hi;
            *(uint2*)(bp + 1 * PLANE + soff + i * 8) = lo;
            cvt4(rb[i], hi, lo);
            *(uint2*)(bp + 2 * PLANE + soff + i * 8) = hi;
            *(uint2*)(bp + 3 * PLANE + soff + i * 8) = lo;
        }
        if (c < 31) {
#pragma unroll
            for (int i = 0; i < 4; i++) {
                ra[i] = *(const float4*)(Ap + (c + 1) * 32 + i * 4);
                rb[i] = *(const float4*)(Wp + (c + 1) * 32 + i * 4);
            }
        }
        __syncthreads();

        const uint32_t bufb = sbase + buf * BUFSZ;
#pragma unroll
        for (int ks = 0; ks < 2; ks++) {
            const int kcol = ks * 16 + (lane >> 4) * 8;
            uint32_t a_hi[2][4], a_lo[2][4];
#pragma unroll
            for (int mi = 0; mi < 2; mi++) {
                int arow = warp_m0 + mi * 16 + (lane & 15);
                uint32_t ad = bufb + arow * (ASTR * 2) + kcol * 2;
                ldsm_x4(a_hi[mi], ad);
                ldsm_x4(a_lo[mi], ad + PLANE);
            }
#pragma unroll
            for (int nt = 0; nt < 4; nt++) {
                uint32_t b_hi[4], b_lo[4];
                int brow = warp_n0 + nt * 16 + (lane & 15);
                uint32_t bd = bufb + 2 * PLANE + brow * (ASTR * 2) + kcol * 2;
                ldsm_x4(b_hi, bd);
                ldsm_x4(b_lo, bd + PLANE);
#pragma unroll
                for (int mi = 0; mi < 2; mi++) {
                    mma16816(acc[mi][nt * 2 + 0], a_hi[mi], b_hi[0], b_hi[2]);
                    mma16816(acc[mi][nt * 2 + 1], a_hi[mi], b_hi[1], b_hi[3]);
                    mma16816(acc[mi][nt * 2 + 0], a_hi[mi], b_lo[0], b_lo[2]);
                    mma16816(acc[mi][nt * 2 + 1], a_hi[mi], b_lo[1], b_lo[3]);
                    mma16816(acc[mi][nt * 2 + 0], a_lo[mi], b_hi[0], b_hi[2]);
                    mma16816(acc[mi][nt * 2 + 1], a_lo[mi], b_hi[1], b_hi[3]);
                }
            }
        }
        __syncthreads();
    }

#pragma unroll
    for (int mi = 0; mi < 2; mi++) {
#pragma unroll
        for (int h2 = 0; h2 < 2; h2++) {
            int n = bm + warp_m0 + mi * 16 + (lane >> 2) + h2 * 8;
            int b = n >> 10;
            int s = n & 1023;
#pragma unroll
            for (int nj = 0; nj < 8; nj++) {
                int o = bn + warp_n0 + nj * 8 + (lane & 3) * 2;
                float2 bb = *(const float2*)&bias[o];
                float2 val;
                val.x = acc[mi][nj][h2 * 2 + 0] + bb.x;
                val.y = acc[mi][nj][h2 * 2 + 1] + bb.y;
                int t = o >> 10;
                int head = (o & 1023) >> 6;
                int dd = o & 63;
                float* dst = (t == 0) ? g_q : (t == 1) ? g_k : g_v;
                *(float2*)&dst[(((size_t)(b << 4) + head) << 16) | (s << 6) | dd] = val;
            }
        }
    }
}

// ---------------------------------------------------------------------------
// Kernel 2: tensor-core fused attention.
// Smem cut to 108.3 KB (D band aliased onto P hi/lo planes -> 2 CTAs/SM).
// QD/KD phase split into halves so acc2 is [4][4] (register cap 128).
// ---------------------------------------------------------------------------
#define TST 144                    // byte stride for 72-bf16 rows
#define OFF_QHI 0
#define OFF_QLO 9216
#define OFF_KHI 18432
#define OFF_KLO 27648
#define OFF_VHI 36864
#define OFF_VLO 46080
#define OFF_QD  55296              // 64 x 260 B = 16640
#define OFF_KD  71936              // 16640
#define OFF_PHI 88576              // 9216  (aliased with D rows 0..63)
#define OFF_PLO 97792              // 9216  (aliased with D rows 64..127)
#define OFF_D   88576              // 128 rows x TST = 18432 (alias of PHI+PLO)
#define OFF_RMAX 107008            // [2][64] f32
#define OFF_RSUM 107520            // [2][64] f32
#define OFF_MASK 108032            // [64] f32
#define ATTN_SMEM 108288
#define QDSTR 260                  // byte stride for QD/KD rows (130 bf16)

__global__ __launch_bounds__(256, 2) void attn_mma_kernel(
    const float* __restrict__ dist,   // [2047,64]
    const float* __restrict__ mask,   // [B,1,1,S]
    float* __restrict__ out)          // [B,S,1024]
{
    extern __shared__ char sm[];
    const uint32_t sb = smem_u32(sm);
    const int tid = threadIdx.x;
    const int w = tid >> 5;
    const int lane = tid & 31;
    const int wm = w >> 1;            // 0..3 -> rows 16*wm
    const int wn = w & 1;             // 0..1 -> cols 32*wn
    const int l0g = blockIdx.x * 64;
    const int bh = blockIdx.y;
    const int b = bh >> 4;
    const int h = bh & 15;

    const float* qg = g_q + (size_t)bh * (SEQ * HDIM);
    const float* kg = g_k + (size_t)bh * (SEQ * HDIM);
    const float* vg = g_v + (size_t)bh * (SEQ * HDIM);

    // ---- load Q tile (once): rows l0g..+63, hi/lo bf16 ----
    {
        const int row = tid >> 2;
        const int c0 = (tid & 3) * 16;
        const float* src = qg + (l0g + row) * 64 + c0;
        char* dhi = sm + OFF_QHI + row * TST + c0 * 2;
        char* dlo = sm + OFF_QLO + row * TST + c0 * 2;
#pragma unroll
        for (int i = 0; i < 4; i++) {
            uint2 hi, lo;
            cvt4(*(const float4*)(src + i * 4), hi, lo);
            *(uint2*)(dhi + i * 8) = hi;
            *(uint2*)(dlo + i * 8) = lo;
        }
    }

    float O[4][4];
#pragma unroll
    for (int i = 0; i < 4; i++)
#pragma unroll
        for (int j = 0; j < 4; j++) O[i][j] = 0.f;
    float m0r = -1e30f, m1r = -1e30f, l0r = 0.f, l1r = 0.f;

    const int lr0 = 16 * wm + (lane >> 2);
    const int lr1 = lr0 + 8;

    for (int r0 = 0; r0 < SEQ; r0 += 64) {
        __syncthreads();  // protects: Q load (iter 0), P planes (prev iter) vs D store
        // ---- load K (hi/lo), V (hi/lo), D band (bf16, into P alias), mask ----
        {
            const int row = tid >> 2;
            const int c0 = (tid & 3) * 16;
            const float* ks = kg + (r0 + row) * 64 + c0;
            const float* vs = vg + (r0 + row) * 64 + c0;
            char* dkh = sm + OFF_KHI + row * TST + c0 * 2;
            char* dkl = sm + OFF_KLO + row * TST + c0 * 2;
            char* dvh = sm + OFF_VHI + row * TST + c0 * 2;
            char* dvl = sm + OFF_VLO + row * TST + c0 * 2;
#pragma unroll
            for (int i = 0; i < 4; i++) {
                uint2 hi, lo;
                cvt4(*(const float4*)(ks + i * 4), hi, lo);
                *(uint2*)(dkh + i * 8) = hi;
                *(uint2*)(dkl + i * 8) = lo;
                cvt4(*(const float4*)(vs + i * 4), hi, lo);
                *(uint2*)(dvh + i * 8) = hi;
                *(uint2*)(dvl + i * 8) = lo;
            }
            // D band: Dband[j] = dist[jb + j], j in [0,127)
            const int jb = l0g - r0 + 960;
            const int drow = tid >> 1;
            const int dc0 = (tid & 1) * 32;
            char* dd = sm + OFF_D + drow * TST + dc0 * 2;
            if (drow < 127) {
                const float* dsrc = dist + (size_t)(jb + drow) * 64 + dc0;
#pragma unroll
                for (int i = 0; i < 8; i++)
                    *(uint2*)(dd + i * 8) = cvt4h(*(const float4*)(dsrc + i * 4));
            } else {
#pragma unroll
                for (int i = 0; i < 8; i++)
                    *(uint2*)(dd + i * 8) = make_uint2(0u, 0u);
            }
            if (tid < 64)
                *(float*)(sm + OFF_MASK + tid * 4) = mask[b * SEQ + r0 + tid];
        }
        __syncthreads();

        // ---- QK scores (hi/lo 3 passes): warp tile 16 x 32 ----
        float accs[4][4];
#pragma unroll
        for (int i = 0; i < 4; i++)
#pragma unroll
            for (int j = 0; j < 4; j++) accs[i][j] = 0.f;

#pragma unroll
        for (int k = 0; k < 4; k++) {
            const int kc = (k * 16 + (lane >> 4) * 8) * 2;
            uint32_t a_hi[4], a_lo[4];
            uint32_t arow = sb + (16 * wm + (lane & 15)) * TST + kc;
            ldsm_x4(a_hi, arow + OFF_QHI);
            ldsm_x4(a_lo, arow + OFF_QLO);
#pragma unroll
            for (int np = 0; np < 2; np++) {
                uint32_t bh4[4], bl4[4];
                uint32_t brow = sb + (32 * wn + 16 * np + (lane & 15)) * TST + kc;
                ldsm_x4(bh4, brow + OFF_KHI);
                ldsm_x4(bl4, brow + OFF_KLO);
                mma16816(accs[2 * np + 0], a_hi, bh4[0], bh4[2]);
                mma16816(accs[2 * np + 1], a_hi, bh4[1], bh4[3]);
                mma16816(accs[2 * np + 0], a_hi, bl4[0], bl4[2]);
                mma16816(accs[2 * np + 1], a_hi, bl4[1], bl4[3]);
                mma16816(accs[2 * np + 0], a_lo, bh4[0], bh4[2]);
                mma16816(accs[2 * np + 1], a_lo, bh4[1], bh4[3]);
            }
        }

        // ---- QD then KD (single bf16 pass, two n-halves to cap regs) ----
#pragma unroll
        for (int pass = 0; pass < 2; pass++) {
            const uint32_t aoff = (pass == 0) ? OFF_QHI : OFF_KHI;
            const uint32_t ooff = (pass == 0) ? OFF_QD : OFF_KD;
#pragma unroll
            for (int half = 0; half < 2; half++) {
                float acc2[4][4];
#pragma unroll
                for (int i = 0; i < 4; i++)
#pragma unroll
                    for (int j = 0; j < 4; j++) acc2[i][j] = 0.f;
#pragma unroll
                for (int k = 0; k < 4; k++) {
                    const int kc = (k * 16 + (lane >> 4) * 8) * 2;
                    uint32_t a4[4];
                    ldsm_x4(a4, sb + aoff + (16 * wm + (lane & 15)) * TST + kc);
#pragma unroll
                    for (int np = 0; np < 2; np++) {
                        const int npg = half * 2 + np;
                        uint32_t b4[4];
                        ldsm_x4(b4, sb + OFF_D + (64 * wn + 16 * npg + (lane & 15)) * TST + kc);
                        mma16816(acc2[2 * np + 0], a4, b4[0], b4[2]);
                        mma16816(acc2[2 * np + 1], a4, b4[1], b4[3]);
                    }
                }
#pragma unroll
                for (int nt = 0; nt < 4; nt++) {
                    const int col = 64 * wn + 8 * (half * 4 + nt) + 2 * (lane & 3);
                    *(uint32_t*)(sm + ooff + lr0 * QDSTR + col * 2) =
                        pack_bf16(__float2bfloat16_rn(acc2[nt][0]),
                                  __float2bfloat16_rn(acc2[nt][1]));
                    *(uint32_t*)(sm + ooff + lr1 * QDSTR + col * 2) =
                        pack_bf16(__float2bfloat16_rn(acc2[nt][2]),
                                  __float2bfloat16_rn(acc2[nt][3]));
                }
            }
        }
        __syncthreads();

        // ---- gather + scale + mask ----
        const __nv_bfloat16* QDp = (const __nv_bfloat16*)(sm + OFF_QD);
        const __nv_bfloat16* KDp = (const __nv_bfloat16*)(sm + OFF_KD);
        const float* msk = (const float*)(sm + OFF_MASK);
#pragma unroll
        for (int nt = 0; nt < 4; nt++) {
            const int c = 32 * wn + 8 * nt + 2 * (lane & 3);
#pragma unroll
            for (int e = 0; e < 4; e++) {
                const int row = (e < 2) ? lr0 : lr1;
                const int col = c + (e & 1);
                const int j = row - col + 63;
                float v = accs[nt][e]
                        + __bfloat162float(QDp[row * 130 + j])
                        + __bfloat162float(KDp[col * 130 + j]);
                accs[nt][e] = v * 0.125f + msk[col];
            }
        }

        // ---- online softmax ----
        float vmax0 = -1e30f, vmax1 = -1e30f;
#pragma unroll
        for (int nt = 0; nt < 4; nt++) {
            vmax0 = fmaxf(vmax0, fmaxf(accs[nt][0], accs[nt][1]));
            vmax1 = fmaxf(vmax1, fmaxf(accs[nt][2], accs[nt][3]));
        }
#pragma unroll
        for (int off = 1; off < 4; off <<= 1) {
            vmax0 = fmaxf(vmax0, __shfl_xor_sync(0xffffffffu, vmax0, off));
            vmax1 = fmaxf(vmax1, __shfl_xor_sync(0xffffffffu, vmax1, off));
        }
        float* rmax = (float*)(sm + OFF_RMAX);
        if ((lane & 3) == 0) {
            rmax[wn * 64 + lr0] = vmax0;
            rmax[wn * 64 + lr1] = vmax1;
        }
        __syncthreads();
        const float mn0 = fmaxf(m0r, fmaxf(rmax[lr0], rmax[64 + lr0]));
        const float mn1 = fmaxf(m1r, fmaxf(rmax[lr1], rmax[64 + lr1]));
        const float corr0 = __expf(m0r - mn0);
        const float corr1 = __expf(m1r - mn1);
        m0r = mn0; m1r = mn1;

        float vsum0 = 0.f, vsum1 = 0.f;
#pragma unroll
        for (int nt = 0; nt < 4; nt++) {
            accs[nt][0] = __expf(accs[nt][0] - mn0);
            accs[nt][1] = __expf(accs[nt][1] - mn0);
            accs[nt][2] = __expf(accs[nt][2] - mn1);
            accs[nt][3] = __expf(accs[nt][3] - mn1);
            vsum0 += accs[nt][0] + accs[nt][1];
            vsum1 += accs[nt][2] + accs[nt][3];
        }
#pragma unroll
        for (int off = 1; off < 4; off <<= 1) {
            vsum0 += __shfl_xor_sync(0xffffffffu, vsum0, off);
            vsum1 += __shfl_xor_sync(0xffffffffu, vsum1, off);
        }
        float* rsum = (float*)(sm + OFF_RSUM);
        if ((lane & 3) == 0) {
            rsum[wn * 64 + lr0] = vsum0;
            rsum[wn * 64 + lr1] = vsum1;
        }
        // stage P hi/lo (overwrites D alias — D dead after QD/KD phase)
#pragma unroll
        for (int nt = 0; nt < 4; nt++) {
            const int col = 32 * wn + 8 * nt + 2 * (lane & 3);
            __nv_bfloat16 h0 = __float2bfloat16_rn(accs[nt][0]);
            __nv_bfloat16 h1 = __float2bfloat16_rn(accs[nt][1]);
            __nv_bfloat16 h2 = __float2bfloat16_rn(accs[nt][2]);
            __nv_bfloat16 h3 = __float2bfloat16_rn(accs[nt][3]);
            *(uint32_t*)(sm + OFF_PHI + lr0 * TST + col * 2) = pack_bf16(h0, h1);
            *(uint32_t*)(sm + OFF_PHI + lr1 * TST + col * 2) = pack_bf16(h2, h3);
            *(uint32_t*)(sm + OFF_PLO + lr0 * TST + col * 2) = pack_bf16(
                __float2bfloat16_rn(accs[nt][0] - __bfloat162float(h0)),
                __float2bfloat16_rn(accs[nt][1] - __bfloat162float(h1)));
            *(uint32_t*)(sm + OFF_PLO + lr1 * TST + col * 2) = pack_bf16(
                __float2bfloat16_rn(accs[nt][2] - __bfloat162float(h2)),
                __float2bfloat16_rn(accs[nt][3] - __bfloat162float(h3)));
        }
        // rescale O
#pragma unroll
        for (int nt = 0; nt < 4; nt++) {
            O[nt][0] *= corr0; O[nt][1] *= corr0;
            O[nt][2] *= corr1; O[nt][3] *= corr1;
        }
        __syncthreads();
        l0r = l0r * corr0 + rsum[lr0] + rsum[64 + lr0];
        l1r = l1r * corr1 + rsum[lr1] + rsum[64 + lr1];

        // ---- O += P @ V (hi/lo x hi/lo, 3 passes) ----
#pragma unroll
        for (int k = 0; k < 4; k++) {
            const int kc = (k * 16 + (lane >> 4) * 8) * 2;
            uint32_t a_hi[4], a_lo[4];
            uint32_t arow = sb + (16 * wm + (lane & 15)) * TST + kc;
            ldsm_x4(a_hi, arow + OFF_PHI);
            ldsm_x4(a_lo, arow + OFF_PLO);
#pragma unroll
            for (int np = 0; np < 2; np++) {
                uint32_t bth[4], btl[4];
                const uint32_t vaddr = sb + (k * 16 + (lane & 15)) * TST
                              + (32 * wn + 16 * np + (lane >> 4) * 8) * 2;
                ldsm_x4_t(bth, vaddr + OFF_VHI);
                ldsm_x4_t(btl, vaddr + OFF_VLO);
                mma16816(O[2 * np + 0], a_hi, bth[0], bth[1]);
                mma16816(O[2 * np + 1], a_hi, bth[2], bth[3]);
                mma16816(O[2 * np + 0], a_hi, btl[0], btl[1]);
                mma16816(O[2 * np + 1], a_hi, btl[2], btl[3]);
                mma16816(O[2 * np + 0], a_lo, bth[0], bth[1]);
                mma16816(O[2 * np + 1], a_lo, bth[2], bth[3]);
            }
        }
    }

    // ---- epilogue ----
    const float inv0 = 1.f / l0r;
    const float inv1 = 1.f / l1r;
#pragma unroll
    for (int nt = 0; nt < 4; nt++) {
        const int dcol = 32 * wn + 8 * nt + 2 * (lane & 3);
        float2 o0 = make_float2(O[nt][0] * inv0, O[nt][1] * inv0);
        float2 o1 = make_float2(O[nt][2] * inv1, O[nt][3] * inv1);
        *(float2*)&out[((size_t)(b * SEQ) + l0g + lr0) * 1024 + h * 64 + dcol] = o0;
        *(float2*)&out[((size_t)(b * SEQ) + l0g + lr1) * 1024 + h * 64 + dcol] = o1;
    }
}

// ---------------------------------------------------------------------------
extern "C" void kernel_launch(void* const* d_in, const int* in_sizes, int n_in,
                              void* d_out, int out_size) {
    const float* hs     = (const float*)d_in[0];  // [4,1024,1024]
    const float* qkv_w  = (const float*)d_in[1];  // [3072,1024]
    const float* qkv_b  = (const float*)d_in[2];  // [3072]
    const float* dist   = (const float*)d_in[3];  // [2047,64]
    const float* emask  = (const float*)d_in[4];  // [4,1,1,1024]
    float* out = (float*)d_out;

    cudaFuncSetAttribute(qkv_mma_kernel,
                         cudaFuncAttributeMaxDynamicSharedMemorySize, QKV_SMEM);
    dim3 g1(3072 / 128, 4096 / 128);
    qkv_mma_kernel<<<g1, 256, QKV_SMEM>>>(hs, qkv_w, qkv_b);

    cudaFuncSetAttribute(attn_mma_kernel,
                         cudaFuncAttributeMaxDynamicSharedMemorySize, ATTN_SMEM);
    dim3 g2(SEQ / 64, BHD);
    attn_mma_kernel<<<g2, 256, ATTN_SMEM>>>(dist, emask, out);
}

// round 10
// speedup vs baseline: 2.8079x; 1.0294x over previous
#include <cuda_runtime.h>
#include <cuda_bf16.h>
#include <cstdint>

#define BATCH 4
#define SEQ 1024
#define NHEADS 16
#define HDIM 64
#define BHD (BATCH*NHEADS)          // 64
#define QKV_ELEMS (BATCH*NHEADS*SEQ*HDIM)  // 4,194,304

__device__ float g_q[QKV_ELEMS];
__device__ float g_k[QKV_ELEMS];
__device__ float g_v[QKV_ELEMS];

// ---------------------------------------------------------------------------
// helpers
// ---------------------------------------------------------------------------
__device__ __forceinline__ uint32_t smem_u32(const void* p) {
    uint32_t a;
    asm("{ .reg .u64 t; cvta.to.shared.u64 t, %1; cvt.u32.u64 %0, t; }"
        : "=r"(a) : "l"(p));
    return a;
}

__device__ __forceinline__ void ldsm_x4(uint32_t* r, uint32_t addr) {
    asm volatile("ldmatrix.sync.aligned.m8n8.x4.shared.b16 {%0,%1,%2,%3}, [%4];"
                 : "=r"(r[0]), "=r"(r[1]), "=r"(r[2]), "=r"(r[3]) : "r"(addr));
}

__device__ __forceinline__ void ldsm_x4_t(uint32_t* r, uint32_t addr) {
    asm volatile("ldmatrix.sync.aligned.m8n8.x4.trans.shared.b16 {%0,%1,%2,%3}, [%4];"
                 : "=r"(r[0]), "=r"(r[1]), "=r"(r[2]), "=r"(r[3]) : "r"(addr));
}

__device__ __forceinline__ void mma16816(float* d, const uint32_t* a,
                                         uint32_t b0, uint32_t b1) {
    asm volatile(
        "mma.sync.aligned.m16n8k16.row.col.f32.bf16.bf16.f32 "
        "{%0,%1,%2,%3}, {%4,%5,%6,%7}, {%8,%9}, {%0,%1,%2,%3};"
        : "+f"(d[0]), "+f"(d[1]), "+f"(d[2]), "+f"(d[3])
        : "r"(a[0]), "r"(a[1]), "r"(a[2]), "r"(a[3]), "r"(b0), "r"(b1));
}

__device__ __forceinline__ uint32_t pack_bf16(__nv_bfloat16 a, __nv_bfloat16 b) {
    return ((uint32_t)__bfloat16_as_ushort(b) << 16) | __bfloat16_as_ushort(a);
}

__device__ __forceinline__ void cvt4(float4 v, uint2& hi, uint2& lo) {
    float f[4] = {v.x, v.y, v.z, v.w};
    __nv_bfloat16 h[4], l[4];
#pragma unroll
    for (int i = 0; i < 4; i++) {
        h[i] = __float2bfloat16_rn(f[i]);
        l[i] = __float2bfloat16_rn(f[i] - __bfloat162float(h[i]));
    }
    hi.x = pack_bf16(h[0], h[1]); hi.y = pack_bf16(h[2], h[3]);
    lo.x = pack_bf16(l[0], l[1]); lo.y = pack_bf16(l[2], l[3]);
}

__device__ __forceinline__ uint2 cvt4h(float4 v) {
    uint2 hi;
    hi.x = pack_bf16(__float2bfloat16_rn(v.x), __float2bfloat16_rn(v.y));
    hi.y = pack_bf16(__float2bfloat16_rn(v.z), __float2bfloat16_rn(v.w));
    return hi;
}

// ---------------------------------------------------------------------------
// Kernel 1: QKV projection via mma.sync bf16x3 (unchanged).
// ---------------------------------------------------------------------------
#define ASTR 40
#define PLANE (128 * ASTR * 2)
#define BUFSZ (4 * PLANE)
#define QKV_SMEM (2 * BUFSZ)

__global__ __launch_bounds__(256, 2) void qkv_mma_kernel(
    const float* __restrict__ A,
    const float* __restrict__ W,
    const float* __restrict__ bias)
{
    extern __shared__ char sm[];
    const uint32_t sbase = smem_u32(sm);
    const int tid = threadIdx.x;
    const int w = tid >> 5;
    const int lane = tid & 31;
    const int bm = blockIdx.y * 128;
    const int bn = blockIdx.x * 128;
    const int warp_m0 = (w >> 1) * 32;
    const int warp_n0 = (w & 1) * 64;

    float acc[2][8][4];
#pragma unroll
    for (int i = 0; i < 2; i++)
#pragma unroll
        for (int j = 0; j < 8; j++)
#pragma unroll
            for (int t = 0; t < 4; t++) acc[i][j][t] = 0.f;

    const int lrow = tid >> 1;
    const int lcol = (tid & 1) * 16;
    const float* Ap = A + (size_t)(bm + lrow) * 1024 + lcol;
    const float* Wp = W + (size_t)(bn + lrow) * 1024 + lcol;
    const int soff = lrow * (ASTR * 2) + lcol * 2;

    float4 ra[4], rb[4];
#pragma unroll
    for (int i = 0; i < 4; i++) {
        ra[i] = *(const float4*)(Ap + i * 4);
        rb[i] = *(const float4*)(Wp + i * 4);
    }

    for (int c = 0; c < 32; c++) {
        const int buf = c & 1;
        char* bp = sm + buf * BUFSZ;
#pragma unroll
        for (int i = 0; i < 4; i++) {
            uint2 hi, lo;
            cvt4(ra[i], hi, lo);
            *(uint2*)(bp + 0 * PLANE + soff + i * 8) = hi;
            *(uint2*)(bp + 1 * PLANE + soff + i * 8) = lo;
            cvt4(rb[i], hi, lo);
            *(uint2*)(bp + 2 * PLANE + soff + i * 8) = hi;
            *(uint2*)(bp + 3 * PLANE + soff + i * 8) = lo;
        }
        if (c < 31) {
#pragma unroll
            for (int i = 0; i < 4; i++) {
                ra[i] = *(const float4*)(Ap + (c + 1) * 32 + i * 4);
                rb[i] = *(const float4*)(Wp + (c + 1) * 32 + i * 4);
            }
        }
        __syncthreads();

        const uint32_t bufb = sbase + buf * BUFSZ;
#pragma unroll
        for (int ks = 0; ks < 2; ks++) {
            const int kcol = ks * 16 + (lane >> 4) * 8;
            uint32_t a_hi[2][4], a_lo[2][4];
#pragma unroll
            for (int mi = 0; mi < 2; mi++) {
                int arow = warp_m0 + mi * 16 + (lane & 15);
                uint32_t ad = bufb + arow * (ASTR * 2) + kcol * 2;
                ldsm_x4(a_hi[mi], ad);
                ldsm_x4(a_lo[mi], ad + PLANE);
            }
#pragma unroll
            for (int nt = 0; nt < 4; nt++) {
                uint32_t b_hi[4], b_lo[4];
                int brow = warp_n0 + nt * 16 + (lane & 15);
                uint32_t bd = bufb + 2 * PLANE + brow * (ASTR * 2) + kcol * 2;
                ldsm_x4(b_hi, bd);
                ldsm_x4(b_lo, bd + PLANE);
#pragma unroll
                for (int mi = 0; mi < 2; mi++) {
                    mma16816(acc[mi][nt * 2 + 0], a_hi[mi], b_hi[0], b_hi[2]);
                    mma16816(acc[mi][nt * 2 + 1], a_hi[mi], b_hi[1], b_hi[3]);
                    mma16816(acc[mi][nt * 2 + 0], a_hi[mi], b_lo[0], b_lo[2]);
                    mma16816(acc[mi][nt * 2 + 1], a_hi[mi], b_lo[1], b_lo[3]);
                    mma16816(acc[mi][nt * 2 + 0], a_lo[mi], b_hi[0], b_hi[2]);
                    mma16816(acc[mi][nt * 2 + 1], a_lo[mi], b_hi[1], b_hi[3]);
                }
            }
        }
        __syncthreads();
    }

#pragma unroll
    for (int mi = 0; mi < 2; mi++) {
#pragma unroll
        for (int h2 = 0; h2 < 2; h2++) {
            int n = bm + warp_m0 + mi * 16 + (lane >> 2) + h2 * 8;
            int b = n >> 10;
            int s = n & 1023;
#pragma unroll
            for (int nj = 0; nj < 8; nj++) {
                int o = bn + warp_n0 + nj * 8 + (lane & 3) * 2;
                float2 bb = *(const float2*)&bias[o];
                float2 val;
                val.x = acc[mi][nj][h2 * 2 + 0] + bb.x;
                val.y = acc[mi][nj][h2 * 2 + 1] + bb.y;
                int t = o >> 10;
                int head = (o & 1023) >> 6;
                int dd = o & 63;
                float* dst = (t == 0) ? g_q : (t == 1) ? g_k : g_v;
                *(float2*)&dst[(((size_t)(b << 4) + head) << 16) | (s << 6) | dd] = val;
            }
        }
    }
}

// ---------------------------------------------------------------------------
// Kernel 2: tensor-core fused attention, P kept in registers (FA-2 style).
// Each warp: score tile 16(wm) x 32(wn); partial O = P(16x32) @ V(32x64)
// accumulated over all r-tiles; wn-pair partials summed in epilogue.
// QD+KD fused in one loop sharing D b-fragments; Q a-fragments cached.
// ---------------------------------------------------------------------------
#define TST 144                    // byte stride for 72-bf16 rows
#define OFF_QHI 0
#define OFF_QLO 9216
#define OFF_KHI 18432
#define OFF_KLO 27648
#define OFF_VHI 36864
#define OFF_VLO 46080
#define OFF_D   55296              // 128 rows x TST = 18432
#define OFF_QD  73728              // 64 x 260 B = 16640 (epilogue O-buf alias)
#define OFF_KD  90368              // 16640
#define OFF_RMAX 107008            // [2][64] f32
#define OFF_RSUM 107520            // [2][64] f32
#define OFF_MASK 108032            // [64] f32
#define ATTN_SMEM 108288
#define QDSTR 260                  // byte stride for QD/KD rows (130 bf16)

__global__ __launch_bounds__(256, 2) void attn_mma_kernel(
    const float* __restrict__ dist,   // [2047,64]
    const float* __restrict__ mask,   // [B,1,1,S]
    float* __restrict__ out)          // [B,S,1024]
{
    extern __shared__ char sm[];
    const uint32_t sb = smem_u32(sm);
    const int tid = threadIdx.x;
    const int w = tid >> 5;
    const int lane = tid & 31;
    const int wm = w >> 1;            // 0..3 -> score rows 16*wm
    const int wn = w & 1;             // 0..1 -> score cols 32*wn
    const int l0g = blockIdx.x * 64;
    const int bh = blockIdx.y;
    const int b = bh >> 4;
    const int h = bh & 15;

    const float* qg = g_q + (size_t)bh * (SEQ * HDIM);
    const float* kg = g_k + (size_t)bh * (SEQ * HDIM);
    const float* vg = g_v + (size_t)bh * (SEQ * HDIM);

    // ---- load Q tile (once): rows l0g..+63, hi/lo bf16 ----
    {
        const int row = tid >> 2;
        const int c0 = (tid & 3) * 16;
        const float* src = qg + (l0g + row) * 64 + c0;
        char* dhi = sm + OFF_QHI + row * TST + c0 * 2;
        char* dlo = sm + OFF_QLO + row * TST + c0 * 2;
#pragma unroll
        for (int i = 0; i < 4; i++) {
            uint2 hi, lo;
            cvt4(*(const float4*)(src + i * 4), hi, lo);
            *(uint2*)(dhi + i * 8) = hi;
            *(uint2*)(dlo + i * 8) = lo;
        }
    }

    // partial O: 16 rows (16*wm) x 64 cols, 8 n8 tiles
    float O[8][4];
#pragma unroll
    for (int i = 0; i < 8; i++)
#pragma unroll
        for (int j = 0; j < 4; j++) O[i][j] = 0.f;
    float m0r = -1e30f, m1r = -1e30f, l0r = 0.f, l1r = 0.f;

    const int lr0 = 16 * wm + (lane >> 2);
    const int lr1 = lr0 + 8;
    const int q2 = 2 * (lane & 3);

    for (int r0 = 0; r0 < SEQ; r0 += 64) {
        __syncthreads();  // prev-iter smem reads all complete
        // ---- load K (hi/lo), V (hi/lo), D band (bf16), mask ----
        {
            const int row = tid >> 2;
            const int c0 = (tid & 3) * 16;
            const float* ks = kg + (r0 + row) * 64 + c0;
            const float* vs = vg + (r0 + row) * 64 + c0;
            char* dkh = sm + OFF_KHI + row * TST + c0 * 2;
            char* dkl = sm + OFF_KLO + row * TST + c0 * 2;
            char* dvh = sm + OFF_VHI + row * TST + c0 * 2;
            char* dvl = sm + OFF_VLO + row * TST + c0 * 2;
#pragma unroll
            for (int i = 0; i < 4; i++) {
                uint2 hi, lo;
                cvt4(*(const float4*)(ks + i * 4), hi, lo);
                *(uint2*)(dkh + i * 8) = hi;
                *(uint2*)(dkl + i * 8) = lo;
                cvt4(*(const float4*)(vs + i * 4), hi, lo);
                *(uint2*)(dvh + i * 8) = hi;
                *(uint2*)(dvl + i * 8) = lo;
            }
            const int jb = l0g - r0 + 960;
            const int drow = tid >> 1;
            const int dc0 = (tid & 1) * 32;
            char* dd = sm + OFF_D + drow * TST + dc0 * 2;
            if (drow < 127) {
                const float* dsrc = dist + (size_t)(jb + drow) * 64 + dc0;
#pragma unroll
                for (int i = 0; i < 8; i++)
                    *(uint2*)(dd + i * 8) = cvt4h(*(const float4*)(dsrc + i * 4));
            } else {
#pragma unroll
                for (int i = 0; i < 8; i++)
                    *(uint2*)(dd + i * 8) = make_uint2(0u, 0u);
            }
            if (tid < 64)
                *(float*)(sm + OFF_MASK + tid * 4) = mask[b * SEQ + r0 + tid];
        }
        __syncthreads();

        // ---- QK scores (hi/lo 3 passes), caching Q hi fragments ----
        uint32_t qa_hi[4][4];
        float accs[4][4];
#pragma unroll
        for (int i = 0; i < 4; i++)
#pragma unroll
            for (int j = 0; j < 4; j++) accs[i][j] = 0.f;

#pragma unroll
        for (int k = 0; k < 4; k++) {
            const int kc = (k * 16 + (lane >> 4) * 8) * 2;
            const uint32_t arow = sb + (16 * wm + (lane & 15)) * TST + kc;
            ldsm_x4(qa_hi[k], arow + OFF_QHI);
            uint32_t a_lo[4];
            ldsm_x4(a_lo, arow + OFF_QLO);
#pragma unroll
            for (int np = 0; np < 2; np++) {
                uint32_t bh4[4], bl4[4];
                const uint32_t brow = sb + (32 * wn + 16 * np + (lane & 15)) * TST + kc;
                ldsm_x4(bh4, brow + OFF_KHI);
                ldsm_x4(bl4, brow + OFF_KLO);
                mma16816(accs[2 * np + 0], qa_hi[k], bh4[0], bh4[2]);
                mma16816(accs[2 * np + 1], qa_hi[k], bh4[1], bh4[3]);
                mma16816(accs[2 * np + 0], qa_hi[k], bl4[0], bl4[2]);
                mma16816(accs[2 * np + 1], qa_hi[k], bl4[1], bl4[3]);
                mma16816(accs[2 * np + 0], a_lo, bh4[0], bh4[2]);
                mma16816(accs[2 * np + 1], a_lo, bh4[1], bh4[3]);
            }
        }

        // ---- QD + KD fused (share D fragments; Q frags cached) ----
#pragma unroll
        for (int half = 0; half < 2; half++) {
            float aq[4][4], ak[4][4];
#pragma unroll
            for (int i = 0; i < 4; i++)
#pragma unroll
                for (int j = 0; j < 4; j++) { aq[i][j] = 0.f; ak[i][j] = 0.f; }
#pragma unroll
            for (int k = 0; k < 4; k++) {
                const int kc = (k * 16 + (lane >> 4) * 8) * 2;
                uint32_t ka4[4];
                ldsm_x4(ka4, sb + OFF_KHI + (16 * wm + (lane & 15)) * TST + kc);
#pragma unroll
                for (int np = 0; np < 2; np++) {
                    const int npg = half * 2 + np;
                    uint32_t b4[4];
                    ldsm_x4(b4, sb + OFF_D + (64 * wn + 16 * npg + (lane & 15)) * TST + kc);
                    mma16816(aq[2 * np + 0], qa_hi[k], b4[0], b4[2]);
                    mma16816(aq[2 * np + 1], qa_hi[k], b4[1], b4[3]);
                    mma16816(ak[2 * np + 0], ka4, b4[0], b4[2]);
                    mma16816(ak[2 * np + 1], ka4, b4[1], b4[3]);
                }
            }
#pragma unroll
            for (int nt = 0; nt < 4; nt++) {
                const int col = 64 * wn + 8 * (half * 4 + nt) + q2;
                *(uint32_t*)(sm + OFF_QD + lr0 * QDSTR + col * 2) =
                    pack_bf16(__float2bfloat16_rn(aq[nt][0]),
                              __float2bfloat16_rn(aq[nt][1]));
                *(uint32_t*)(sm + OFF_QD + lr1 * QDSTR + col * 2) =
                    pack_bf16(__float2bfloat16_rn(aq[nt][2]),
                              __float2bfloat16_rn(aq[nt][3]));
                *(uint32_t*)(sm + OFF_KD + lr0 * QDSTR + col * 2) =
                    pack_bf16(__float2bfloat16_rn(ak[nt][0]),
                              __float2bfloat16_rn(ak[nt][1]));
                *(uint32_t*)(sm + OFF_KD + lr1 * QDSTR + col * 2) =
                    pack_bf16(__float2bfloat16_rn(ak[nt][2]),
                              __float2bfloat16_rn(ak[nt][3]));
            }
        }
        __syncthreads();

        // ---- gather + scale + mask ----
        const __nv_bfloat16* QDp = (const __nv_bfloat16*)(sm + OFF_QD);
        const __nv_bfloat16* KDp = (const __nv_bfloat16*)(sm + OFF_KD);
        const float* msk = (const float*)(sm + OFF_MASK);
#pragma unroll
        for (int nt = 0; nt < 4; nt++) {
            const int c = 32 * wn + 8 * nt + q2;
#pragma unroll
            for (int e = 0; e < 4; e++) {
                const int row = (e < 2) ? lr0 : lr1;
                const int col = c + (e & 1);
                const int j = row - col + 63;
                float v = accs[nt][e]
                        + __bfloat162float(QDp[row * 130 + j])
                        + __bfloat162float(KDp[col * 130 + j]);
                accs[nt][e] = v * 0.125f + msk[col];
            }
        }

        // ---- online softmax ----
        float vmax0 = -1e30f, vmax1 = -1e30f;
#pragma unroll
        for (int nt = 0; nt < 4; nt++) {
            vmax0 = fmaxf(vmax0, fmaxf(accs[nt][0], accs[nt][1]));
            vmax1 = fmaxf(vmax1, fmaxf(accs[nt][2], accs[nt][3]));
        }
#pragma unroll
        for (int off = 1; off < 4; off <<= 1) {
            vmax0 = fmaxf(vmax0, __shfl_xor_sync(0xffffffffu, vmax0, off));
            vmax1 = fmaxf(vmax1, __shfl_xor_sync(0xffffffffu, vmax1, off));
        }
        float* rmax = (float*)(sm + OFF_RMAX);
        if ((lane & 3) == 0) {
            rmax[wn * 64 + lr0] = vmax0;
            rmax[wn * 64 + lr1] = vmax1;
        }
        __syncthreads();
        const float mn0 = fmaxf(m0r, fmaxf(rmax[lr0], rmax[64 + lr0]));
        const float mn1 = fmaxf(m1r, fmaxf(rmax[lr1], rmax[64 + lr1]));
        const float corr0 = __expf(m0r - mn0);
        const float corr1 = __expf(m1r - mn1);
        m0r = mn0; m1r = mn1;

        float vsum0 = 0.f, vsum1 = 0.f;
#pragma unroll
        for (int nt = 0; nt < 4; nt++) {
            accs[nt][0] = __expf(accs[nt][0] - mn0);
            accs[nt][1] = __expf(accs[nt][1] - mn0);
            accs[nt][2] = __expf(accs[nt][2] - mn1);
            accs[nt][3] = __expf(accs[nt][3] - mn1);
            vsum0 += accs[nt][0] + accs[nt][1];
            vsum1 += accs[nt][2] + accs[nt][3];
        }
#pragma unroll
        for (int off = 1; off < 4; off <<= 1) {
            vsum0 += __shfl_xor_sync(0xffffffffu, vsum0, off);
            vsum1 += __shfl_xor_sync(0xffffffffu, vsum1, off);
        }
        float* rsum = (float*)(sm + OFF_RSUM);
        if ((lane & 3) == 0) {
            rsum[wn * 64 + lr0] = vsum0;
            rsum[wn * 64 + lr1] = vsum1;
        }
        // rescale partial O
#pragma unroll
        for (int nt = 0; nt < 8; nt++) {
            O[nt][0] *= corr0; O[nt][1] *= corr0;
            O[nt][2] *= corr1; O[nt][3] *= corr1;
        }
        __syncthreads();
        l0r = l0r * corr0 + rsum[lr0] + rsum[64 + lr0];
        l1r = l1r * corr1 + rsum[lr1] + rsum[64 + lr1];

        // ---- O_partial += P(16x32, in regs) @ V(32 rows of this wn, 64 cols) ----
#pragma unroll
        for (int ks = 0; ks < 2; ks++) {
            uint32_t a_hi[4], a_lo[4];
#pragma unroll
            for (int hf = 0; hf < 2; hf++) {
                const int nt = 2 * ks + hf;
                __nv_bfloat16 h0 = __float2bfloat16_rn(accs[nt][0]);
                __nv_bfloat16 h1 = __float2bfloat16_rn(accs[nt][1]);
                __nv_bfloat16 h2 = __float2bfloat16_rn(accs[nt][2]);
                __nv_bfloat16 h3 = __float2bfloat16_rn(accs[nt][3]);
                a_hi[2 * hf + 0] = pack_bf16(h0, h1);
                a_hi[2 * hf + 1] = pack_bf16(h2, h3);
                a_lo[2 * hf + 0] = pack_bf16(
                    __float2bfloat16_rn(accs[nt][0] - __bfloat162float(h0)),
                    __float2bfloat16_rn(accs[nt][1] - __bfloat162float(h1)));
                a_lo[2 * hf + 1] = pack_bf16(
                    __float2bfloat16_rn(accs[nt][2] - __bfloat162float(h2)),
                    __float2bfloat16_rn(accs[nt][3] - __bfloat162float(h3)));
            }
            const uint32_t vrow = sb + (32 * wn + 16 * ks + (lane & 15)) * TST;
#pragma unroll
            for (int ng = 0; ng < 4; ng++) {
                uint32_t bth[4], btl[4];
                const uint32_t vaddr = vrow + (16 * ng + (lane >> 4) * 8) * 2;
                ldsm_x4_t(bth, vaddr + OFF_VHI);
                ldsm_x4_t(btl, vaddr + OFF_VLO);
                mma16816(O[2 * ng + 0], a_hi, bth[0], bth[1]);
                mma16816(O[2 * ng + 1], a_hi, bth[2], bth[3]);
                mma16816(O[2 * ng + 0], a_hi, btl[0], btl[1]);
                mma16816(O[2 * ng + 1], a_hi, btl[2], btl[3]);
                mma16816(O[2 * ng + 0], a_lo, bth[0], bth[1]);
                mma16816(O[2 * ng + 1], a_lo, bth[2], bth[3]);
            }
        }
    }

    // ---- epilogue: sum wn-pair partials via smem (alias QD region) ----
    __syncthreads();
    if (wn == 0) {
        float* ob = (float*)(sm + OFF_QD);
#pragma unroll
        for (int t = 0; t < 8; t++) {
            const int col = 8 * t + q2;
            *(float2*)&ob[wm * 1024 + (lane >> 2) * 64 + col] =
                make_float2(O[t][0], O[t][1]);
            *(float2*)&ob[wm * 1024 + ((lane >> 2) + 8) * 64 + col] =
                make_float2(O[t][2], O[t][3]);
        }
    }
    __syncthreads();
    if (wn == 1) {
        const float inv0 = 1.f / l0r;
        const float inv1 = 1.f / l1r;
        const float* ob = (const float*)(sm + OFF_QD);
#pragma unroll
        for (int t = 0; t < 8; t++) {
            const int col = 8 * t + q2;
            float2 p0 = *(const float2*)&ob[wm * 1024 + (lane >> 2) * 64 + col];
            float2 p1 = *(const float2*)&ob[wm * 1024 + ((lane >> 2) + 8) * 64 + col];
            float2 o0 = make_float2((O[t][0] + p0.x) * inv0, (O[t][1] + p0.y) * inv0);
            float2 o1 = make_float2((O[t][2] + p1.x) * inv1, (O[t][3] + p1.y) * inv1);
            *(float2*)&out[((size_t)(b * SEQ) + l0g + lr0) * 1024 + h * 64 + col] = o0;
            *(float2*)&out[((size_t)(b * SEQ) + l0g + lr1) * 1024 + h * 64 + col] = o1;
        }
    }
}

// ---------------------------------------------------------------------------
extern "C" void kernel_launch(void* const* d_in, const int* in_sizes, int n_in,
                              void* d_out, int out_size) {
    const float* hs     = (const float*)d_in[0];  // [4,1024,1024]
    const float* qkv_w  = (const float*)d_in[1];  // [3072,1024]
    const float* qkv_b  = (const float*)d_in[2];  // [3072]
    const float* dist   = (const float*)d_in[3];  // [2047,64]
    const float* emask  = (const float*)d_in[4];  // [4,1,1,1024]
    float* out = (float*)d_out;

    cudaFuncSetAttribute(qkv_mma_kernel,
                         cudaFuncAttributeMaxDynamicSharedMemorySize, QKV_SMEM);
    dim3 g1(3072 / 128, 4096 / 128);
    qkv_mma_kernel<<<g1, 256, QKV_SMEM>>>(hs, qkv_w, qkv_b);

    cudaFuncSetAttribute(attn_mma_kernel,
                         cudaFuncAttributeMaxDynamicSharedMemorySize, ATTN_SMEM);
    dim3 g2(SEQ / 64, BHD);
    attn_mma_kernel<<<g2, 256, ATTN_SMEM>>>(dist, emask, out);
}

// round 13
// speedup vs baseline: 2.9478x; 1.0499x over previous
#include <cuda_runtime.h>
#include <cuda_bf16.h>
#include <cstdint>

#define BATCH 4
#define SEQ 1024
#define NHEADS 16
#define HDIM 64
#define BHD (BATCH*NHEADS)          // 64
#define QKV_ELEMS (BATCH*NHEADS*SEQ*HDIM)  // 4,194,304

__device__ float g_q[QKV_ELEMS];
__device__ float g_k[QKV_ELEMS];
__device__ float g_v[QKV_ELEMS];

// ---------------------------------------------------------------------------
// helpers
// ---------------------------------------------------------------------------
__device__ __forceinline__ uint32_t smem_u32(const void* p) {
    uint32_t a;
    asm("{ .reg .u64 t; cvta.to.shared.u64 t, %1; cvt.u32.u64 %0, t; }"
        : "=r"(a) : "l"(p));
    return a;
}

__device__ __forceinline__ void ldsm_x4(uint32_t* r, uint32_t addr) {
    asm volatile("ldmatrix.sync.aligned.m8n8.x4.shared.b16 {%0,%1,%2,%3}, [%4];"
                 : "=r"(r[0]), "=r"(r[1]), "=r"(r[2]), "=r"(r[3]) : "r"(addr));
}

__device__ __forceinline__ void ldsm_x4_t(uint32_t* r, uint32_t addr) {
    asm volatile("ldmatrix.sync.aligned.m8n8.x4.trans.shared.b16 {%0,%1,%2,%3}, [%4];"
                 : "=r"(r[0]), "=r"(r[1]), "=r"(r[2]), "=r"(r[3]) : "r"(addr));
}

__device__ __forceinline__ void mma16816(float* d, const uint32_t* a,
                                         uint32_t b0, uint32_t b1) {
    asm volatile(
        "mma.sync.aligned.m16n8k16.row.col.f32.bf16.bf16.f32 "
        "{%0,%1,%2,%3}, {%4,%5,%6,%7}, {%8,%9}, {%0,%1,%2,%3};"
        : "+f"(d[0]), "+f"(d[1]), "+f"(d[2]), "+f"(d[3])
        : "r"(a[0]), "r"(a[1]), "r"(a[2]), "r"(a[3]), "r"(b0), "r"(b1));
}

__device__ __forceinline__ uint32_t pack_bf16(__nv_bfloat16 a, __nv_bfloat16 b) {
    return ((uint32_t)__bfloat16_as_ushort(b) << 16) | __bfloat16_as_ushort(a);
}

__device__ __forceinline__ void cvt4(float4 v, uint2& hi, uint2& lo) {
    float f[4] = {v.x, v.y, v.z, v.w};
    __nv_bfloat16 h[4], l[4];
#pragma unroll
    for (int i = 0; i < 4; i++) {
        h[i] = __float2bfloat16_rn(f[i]);
        l[i] = __float2bfloat16_rn(f[i] - __bfloat162float(h[i]));
    }
    hi.x = pack_bf16(h[0], h[1]); hi.y = pack_bf16(h[2], h[3]);
    lo.x = pack_bf16(l[0], l[1]); lo.y = pack_bf16(l[2], l[3]);
}

// 8 floats -> hi uint4 + lo uint4
__device__ __forceinline__ void cvt8(const float* f, uint4& hi, uint4& lo) {
    __nv_bfloat16 h[8], l[8];
#pragma unroll
    for (int i = 0; i < 8; i++) {
        h[i] = __float2bfloat16_rn(f[i]);
        l[i] = __float2bfloat16_rn(f[i] - __bfloat162float(h[i]));
    }
    hi.x = pack_bf16(h[0], h[1]); hi.y = pack_bf16(h[2], h[3]);
    hi.z = pack_bf16(h[4], h[5]); hi.w = pack_bf16(h[6], h[7]);
    lo.x = pack_bf16(l[0], l[1]); lo.y = pack_bf16(l[2], l[3]);
    lo.z = pack_bf16(l[4], l[5]); lo.w = pack_bf16(l[6], l[7]);
}

__device__ __forceinline__ uint4 cvt8h(const float* f) {
    uint4 hi;
    hi.x = pack_bf16(__float2bfloat16_rn(f[0]), __float2bfloat16_rn(f[1]));
    hi.y = pack_bf16(__float2bfloat16_rn(f[2]), __float2bfloat16_rn(f[3]));
    hi.z = pack_bf16(__float2bfloat16_rn(f[4]), __float2bfloat16_rn(f[5]));
    hi.w = pack_bf16(__float2bfloat16_rn(f[6]), __float2bfloat16_rn(f[7]));
    return hi;
}

__device__ __forceinline__ float bf_lo(uint32_t u) {
    return __bfloat162float(__ushort_as_bfloat16((unsigned short)(u & 0xffffu)));
}
__device__ __forceinline__ float bf_hi(uint32_t u) {
    return __bfloat162float(__ushort_as_bfloat16((unsigned short)(u >> 16)));
}

// ---------------------------------------------------------------------------
// Kernel 1: QKV projection via mma.sync bf16x3 (unchanged).
// ---------------------------------------------------------------------------
#define ASTR 40
#define PLANE (128 * ASTR * 2)
#define BUFSZ (4 * PLANE)
#define QKV_SMEM (2 * BUFSZ)

__global__ __launch_bounds__(256, 2) void qkv_mma_kernel(
    const float* __restrict__ A,
    const float* __restrict__ W,
    const float* __restrict__ bias)
{
    extern __shared__ char sm[];
    const uint32_t sbase = smem_u32(sm);
    const int tid = threadIdx.x;
    const int w = tid >> 5;
    const int lane = tid & 31;
    const int bm = blockIdx.y * 128;
    const int bn = blockIdx.x * 128;
    const int warp_m0 = (w >> 1) * 32;
    const int warp_n0 = (w & 1) * 64;

    float acc[2][8][4];
#pragma unroll
    for (int i = 0; i < 2; i++)
#pragma unroll
        for (int j = 0; j < 8; j++)
#pragma unroll
            for (int t = 0; t < 4; t++) acc[i][j][t] = 0.f;

    const int lrow = tid >> 1;
    const int lcol = (tid & 1) * 16;
    const float* Ap = A + (size_t)(bm + lrow) * 1024 + lcol;
    const float* Wp = W + (size_t)(bn + lrow) * 1024 + lcol;
    const int soff = lrow * (ASTR * 2) + lcol * 2;

    float4 ra[4], rb[4];
#pragma unroll
    for (int i = 0; i < 4; i++) {
        ra[i] = *(const float4*)(Ap + i * 4);
        rb[i] = *(const float4*)(Wp + i * 4);
    }

    for (int c = 0; c < 32; c++) {
        const int buf = c & 1;
        char* bp = sm + buf * BUFSZ;
#pragma unroll
        for (int i = 0; i < 4; i++) {
            uint2 hi, lo;
            cvt4(ra[i], hi, lo);
            *(uint2*)(bp + 0 * PLANE + soff + i * 8) = hi;
            *(uint2*)(bp + 1 * PLANE + soff + i * 8) = lo;
            cvt4(rb[i], hi, lo);
            *(uint2*)(bp + 2 * PLANE + soff + i * 8) = hi;
            *(uint2*)(bp + 3 * PLANE + soff + i * 8) = lo;
        }
        if (c < 31) {
#pragma unroll
            for (int i = 0; i < 4; i++) {
                ra[i] = *(const float4*)(Ap + (c + 1) * 32 + i * 4);
                rb[i] = *(const float4*)(Wp + (c + 1) * 32 + i * 4);
            }
        }
        __syncthreads();

        const uint32_t bufb = sbase + buf * BUFSZ;
#pragma unroll
        for (int ks = 0; ks < 2; ks++) {
            const int kcol = ks * 16 + (lane >> 4) * 8;
            uint32_t a_hi[2][4], a_lo[2][4];
#pragma unroll
            for (int mi = 0; mi < 2; mi++) {
                int arow = warp_m0 + mi * 16 + (lane & 15);
                uint32_t ad = bufb + arow * (ASTR * 2) + kcol * 2;
                ldsm_x4(a_hi[mi], ad);
                ldsm_x4(a_lo[mi], ad + PLANE);
            }
#pragma unroll
            for (int nt = 0; nt < 4; nt++) {
                uint32_t b_hi[4], b_lo[4];
                int brow = warp_n0 + nt * 16 + (lane & 15);
                uint32_t bd = bufb + 2 * PLANE + brow * (ASTR * 2) + kcol * 2;
                ldsm_x4(b_hi, bd);
                ldsm_x4(b_lo, bd + PLANE);
#pragma unroll
                for (int mi = 0; mi < 2; mi++) {
                    mma16816(acc[mi][nt * 2 + 0], a_hi[mi], b_hi[0], b_hi[2]);
                    mma16816(acc[mi][nt * 2 + 1], a_hi[mi], b_hi[1], b_hi[3]);
                    mma16816(acc[mi][nt * 2 + 0], a_hi[mi], b_lo[0], b_lo[2]);
                    mma16816(acc[mi][nt * 2 + 1], a_hi[mi], b_lo[1], b_lo[3]);
                    mma16816(acc[mi][nt * 2 + 0], a_lo[mi], b_hi[0], b_hi[2]);
                    mma16816(acc[mi][nt * 2 + 1], a_lo[mi], b_hi[1], b_hi[3]);
                }
            }
        }
        __syncthreads();
    }

#pragma unroll
    for (int mi = 0; mi < 2; mi++) {
#pragma unroll
        for (int h2 = 0; h2 < 2; h2++) {
            int n = bm + warp_m0 + mi * 16 + (lane >> 2) + h2 * 8;
            int b = n >> 10;
            int s = n & 1023;
#pragma unroll
            for (int nj = 0; nj < 8; nj++) {
                int o = bn + warp_n0 + nj * 8 + (lane & 3) * 2;
                float2 bb = *(const float2*)&bias[o];
                float2 val;
                val.x = acc[mi][nj][h2 * 2 + 0] + bb.x;
                val.y = acc[mi][nj][h2 * 2 + 1] + bb.y;
                int t = o >> 10;
                int head = (o & 1023) >> 6;
                int dd = o & 63;
                float* dst = (t == 0) ? g_q : (t == 1) ? g_k : g_v;
                *(float2*)&dst[(((size_t)(b << 4) + head) << 16) | (s << 6) | dd] = val;
            }
        }
    }
}

// ---------------------------------------------------------------------------
// Kernel 2: tensor-core fused attention, P in registers, shifted QDS/KDST
// layouts (conflict-free gather), single pair-scoped softmax exchange.
// QDS stores are scalar bf16 (predicated) — 4-byte stores at odd t0 trap.
// ---------------------------------------------------------------------------
#define TST 144                    // byte stride for 72-bf16 rows
#define OFF_QHI 0
#define OFF_QLO 9216
#define OFF_KHI 18432
#define OFF_KLO 27648
#define OFF_VHI 36864
#define OFF_VLO 46080
#define OFF_D   55296              // 128 rows x TST = 18432
#define OFF_QDS 73728              // 64 rows x 144 B (shifted QD)
#define OFF_KDST 82944             // 64 rows x 144 B (shifted KD^T)
#define OFF_EXCH 92160             // [2][64] float2 = 1024
#define OFF_MASK 93184             // [64] f32
#define ATTN_SMEM 93440

__global__ __launch_bounds__(256, 2) void attn_mma_kernel(
    const float* __restrict__ dist,   // [2047,64]
    const float* __restrict__ mask,   // [B,1,1,S]
    float* __restrict__ out)          // [B,S,1024]
{
    extern __shared__ char sm[];
    const uint32_t sb = smem_u32(sm);
    const int tid = threadIdx.x;
    const int w = tid >> 5;
    const int lane = tid & 31;
    const int wm = w >> 1;            // 0..3 -> score rows 16*wm
    const int wn = w & 1;             // 0..1 -> score cols 32*wn
    const int l0g = blockIdx.x * 64;
    const int bh = blockIdx.y;
    const int b = bh >> 4;
    const int h = bh & 15;

    const float* qg = g_q + (size_t)bh * (SEQ * HDIM);
    const float* kg = g_k + (size_t)bh * (SEQ * HDIM);
    const float* vg = g_v + (size_t)bh * (SEQ * HDIM);

    // ---- load Q tile (once): rows l0g..+63, hi/lo bf16, STS.128 ----
    {
        const int row = tid >> 2;
        const int c0 = (tid & 3) * 16;
        float qf[16];
#pragma unroll
        for (int i = 0; i < 4; i++)
            *(float4*)(qf + i * 4) = *(const float4*)(qg + (l0g + row) * 64 + c0 + i * 4);
        char* dhi = sm + OFF_QHI + row * TST + c0 * 2;
        char* dlo = sm + OFF_QLO + row * TST + c0 * 2;
#pragma unroll
        for (int g = 0; g < 2; g++) {
            uint4 hi, lo;
            cvt8(qf + g * 8, hi, lo);
            *(uint4*)(dhi + g * 16) = hi;
            *(uint4*)(dlo + g * 16) = lo;
        }
    }

    float O[8][4];
#pragma unroll
    for (int i = 0; i < 8; i++)
#pragma unroll
        for (int j = 0; j < 4; j++) O[i][j] = 0.f;
    float m0r = -1e30f, m1r = -1e30f, l0r = 0.f, l1r = 0.f;

    const int lr0 = 16 * wm + (lane >> 2);
    const int lr1 = lr0 + 8;
    const int q2 = 2 * (lane & 3);

    for (int r0 = 0; r0 < SEQ; r0 += 64) {
        __syncthreads();  // prev-iter smem reads all complete
        // ---- fill K/V (hi/lo, STS.128), D band, mask ----
        {
            const int row = tid >> 2;
            const int c0 = (tid & 3) * 16;
            float kf[16], vf[16];
#pragma unroll
            for (int i = 0; i < 4; i++) {
                *(float4*)(kf + i * 4) = *(const float4*)(kg + (r0 + row) * 64 + c0 + i * 4);
                *(float4*)(vf + i * 4) = *(const float4*)(vg + (r0 + row) * 64 + c0 + i * 4);
            }
            char* base = sm + row * TST + c0 * 2;
#pragma unroll
            for (int g = 0; g < 2; g++) {
                uint4 hi, lo;
                cvt8(kf + g * 8, hi, lo);
                *(uint4*)(base + OFF_KHI + g * 16) = hi;
                *(uint4*)(base + OFF_KLO + g * 16) = lo;
                cvt8(vf + g * 8, hi, lo);
                *(uint4*)(base + OFF_VHI + g * 16) = hi;
                *(uint4*)(base + OFF_VLO + g * 16) = lo;
            }
            const int jb = l0g - r0 + 960;
            const int drow = tid >> 1;
            const int dc0 = (tid & 1) * 32;
            char* dd = sm + OFF_D + drow * TST + dc0 * 2;
            if (drow < 127) {
                float df[32];
#pragma unroll
                for (int i = 0; i < 8; i++)
                    *(float4*)(df + i * 4) =
                        *(const float4*)(dist + (size_t)(jb + drow) * 64 + dc0 + i * 4);
#pragma unroll
                for (int g = 0; g < 4; g++)
                    *(uint4*)(dd + g * 16) = cvt8h(df + g * 8);
            } else {
#pragma unroll
                for (int g = 0; g < 4; g++)
                    *(uint4*)(dd + g * 16) = make_uint4(0u, 0u, 0u, 0u);
            }
            if (tid < 64)
                *(float*)(sm + OFF_MASK + tid * 4) = mask[b * SEQ + r0 + tid];
        }
        __syncthreads();

        // ---- QK scores (hi/lo 3 passes), caching Q hi fragments ----
        uint32_t qa_hi[4][4];
        float accs[4][4];
#pragma unroll
        for (int i = 0; i < 4; i++)
#pragma unroll
            for (int j = 0; j < 4; j++) accs[i][j] = 0.f;

#pragma unroll
        for (int k = 0; k < 4; k++) {
            const int kc = (k * 16 + (lane >> 4) * 8) * 2;
            const uint32_t arow = sb + (16 * wm + (lane & 15)) * TST + kc;
            ldsm_x4(qa_hi[k], arow + OFF_QHI);
            uint32_t a_lo[4];
            ldsm_x4(a_lo, arow + OFF_QLO);
#pragma unroll
            for (int np = 0; np < 2; np++) {
                uint32_t bh4[4], bl4[4];
                const uint32_t brow = sb + (32 * wn + 16 * np + (lane & 15)) * TST + kc;
                ldsm_x4(bh4, brow + OFF_KHI);
                ldsm_x4(bl4, brow + OFF_KLO);
                mma16816(accs[2 * np + 0], qa_hi[k], bh4[0], bh4[2]);
                mma16816(accs[2 * np + 1], qa_hi[k], bh4[1], bh4[3]);
                mma16816(accs[2 * np + 0], qa_hi[k], bl4[0], bl4[2]);
                mma16816(accs[2 * np + 1], qa_hi[k], bl4[1], bl4[3]);
                mma16816(accs[2 * np + 0], a_lo, bh4[0], bh4[2]);
                mma16816(accs[2 * np + 1], a_lo, bh4[1], bh4[3]);
            }
        }

        // ---- QD + KD fused, predicated shifted scalar stores ----
#pragma unroll
        for (int half = 0; half < 2; half++) {
            float aq[4][4], ak[4][4];
#pragma unroll
            for (int i = 0; i < 4; i++)
#pragma unroll
                for (int j = 0; j < 4; j++) { aq[i][j] = 0.f; ak[i][j] = 0.f; }
#pragma unroll
            for (int k = 0; k < 4; k++) {
                const int kc = (k * 16 + (lane >> 4) * 8) * 2;
                uint32_t ka4[4];
                ldsm_x4(ka4, sb + OFF_KHI + (16 * wm + (lane & 15)) * TST + kc);
#pragma unroll
                for (int np = 0; np < 2; np++) {
                    const int npg = half * 2 + np;
                    uint32_t b4[4];
                    ldsm_x4(b4, sb + OFF_D + (64 * wn + 16 * npg + (lane & 15)) * TST + kc);
                    mma16816(aq[2 * np + 0], qa_hi[k], b4[0], b4[2]);
                    mma16816(aq[2 * np + 1], qa_hi[k], b4[1], b4[3]);
                    mma16816(ak[2 * np + 0], ka4, b4[0], b4[2]);
                    mma16816(ak[2 * np + 1], ka4, b4[1], b4[3]);
                }
            }
#pragma unroll
            for (int nt = 0; nt < 4; nt++) {
                const int jcol = 64 * wn + 8 * (half * 4 + nt) + q2;
#pragma unroll
                for (int rr = 0; rr < 2; rr++) {
                    const int row = rr ? lr1 : lr0;
                    // QDS[row][t] = QD[row][row + t]; t0 = jcol - row (scalar stores)
                    const int t0 = jcol - row;
                    char* qb = sm + OFF_QDS + row * TST;
                    if (t0 >= 0 && t0 < 64)
                        *(__nv_bfloat16*)(qb + t0 * 2) =
                            __float2bfloat16_rn(aq[nt][rr * 2 + 0]);
                    if (t0 + 1 >= 0 && t0 + 1 < 64)
                        *(__nv_bfloat16*)(qb + (t0 + 1) * 2) =
                            __float2bfloat16_rn(aq[nt][rr * 2 + 1]);
                    // KDST[j + m - 63][m] = KD[m][j]
                    const int r0s = jcol + row - 63;
                    char* kb = sm + OFF_KDST + row * 2;
                    if (r0s >= 0 && r0s < 64)
                        *(__nv_bfloat16*)(kb + r0s * TST) =
                            __float2bfloat16_rn(ak[nt][rr * 2 + 0]);
                    if (r0s + 1 >= 0 && r0s + 1 < 64)
                        *(__nv_bfloat16*)(kb + (r0s + 1) * TST) =
                            __float2bfloat16_rn(ak[nt][rr * 2 + 1]);
                }
            }
        }
        __syncthreads();

        // ---- gather (vectorized) + scale + mask ----
        const float* msk = (const float*)(sm + OFF_MASK);
#pragma unroll
        for (int nt = 0; nt < 4; nt++) {
            const int c = 32 * wn + 8 * nt + q2;
            const uint32_t qd0 = *(const uint32_t*)(sm + OFF_QDS + lr0 * TST + (62 - c) * 2);
            const uint32_t qd1 = *(const uint32_t*)(sm + OFF_QDS + lr1 * TST + (62 - c) * 2);
            const uint32_t kd0 = *(const uint32_t*)(sm + OFF_KDST + lr0 * TST + c * 2);
            const uint32_t kd1 = *(const uint32_t*)(sm + OFF_KDST + lr1 * TST + c * 2);
            const float mk0 = msk[c], mk1 = msk[c + 1];
            accs[nt][0] = (accs[nt][0] + bf_hi(qd0) + bf_lo(kd0)) * 0.125f + mk0;
            accs[nt][1] = (accs[nt][1] + bf_lo(qd0) + bf_hi(kd0)) * 0.125f + mk1;
            accs[nt][2] = (accs[nt][2] + bf_hi(qd1) + bf_lo(kd1)) * 0.125f + mk0;
            accs[nt][3] = (accs[nt][3] + bf_lo(qd1) + bf_hi(kd1)) * 0.125f + mk1;
        }

        // ---- softmax: local max/sum, single pair exchange ----
        float m0 = -1e30f, m1 = -1e30f;
#pragma unroll
        for (int nt = 0; nt < 4; nt++) {
            m0 = fmaxf(m0, fmaxf(accs[nt][0], accs[nt][1]));
            m1 = fmaxf(m1, fmaxf(accs[nt][2], accs[nt][3]));
        }
#pragma unroll
        for (int off = 1; off < 4; off <<= 1) {
            m0 = fmaxf(m0, __shfl_xor_sync(0xffffffffu, m0, off));
            m1 = fmaxf(m1, __shfl_xor_sync(0xffffffffu, m1, off));
        }
        float s0 = 0.f, s1 = 0.f;
#pragma unroll
        for (int nt = 0; nt < 4; nt++) {
            accs[nt][0] = __expf(accs[nt][0] - m0);
            accs[nt][1] = __expf(accs[nt][1] - m0);
            accs[nt][2] = __expf(accs[nt][2] - m1);
            accs[nt][3] = __expf(accs[nt][3] - m1);
            s0 += accs[nt][0] + accs[nt][1];
            s1 += accs[nt][2] + accs[nt][3];
        }
#pragma unroll
        for (int off = 1; off < 4; off <<= 1) {
            s0 += __shfl_xor_sync(0xffffffffu, s0, off);
            s1 += __shfl_xor_sync(0xffffffffu, s1, off);
        }
        float2* exch = (float2*)(sm + OFF_EXCH);
        if ((lane & 3) == 0) {
            exch[wn * 64 + lr0] = make_float2(m0, s0);
            exch[wn * 64 + lr1] = make_float2(m1, s1);
        }
        asm volatile("bar.sync %0, %1;" :: "r"(wm + 1), "r"(64) : "memory");
        const float2 o0 = exch[(wn ^ 1) * 64 + lr0];
        const float2 o1 = exch[(wn ^ 1) * 64 + lr1];
        const float mn0 = fmaxf(m0r, fmaxf(m0, o0.x));
        const float mn1 = fmaxf(m1r, fmaxf(m1, o1.x));
        const float corr0 = __expf(m0r - mn0);
        const float corr1 = __expf(m1r - mn1);
        const float ps0 = __expf(m0 - mn0);
        const float ps1 = __expf(m1 - mn1);
        l0r = l0r * corr0 + s0 * ps0 + o0.y * __expf(o0.x - mn0);
        l1r = l1r * corr1 + s1 * ps1 + o1.y * __expf(o1.x - mn1);
        m0r = mn0; m1r = mn1;
#pragma unroll
        for (int nt = 0; nt < 8; nt++) {
            O[nt][0] *= corr0; O[nt][1] *= corr0;
            O[nt][2] *= corr1; O[nt][3] *= corr1;
        }

        // ---- O_partial += P(scaled, in regs) @ V(32 rows of this wn) ----
#pragma unroll
        for (int ks = 0; ks < 2; ks++) {
            uint32_t a_hi[4], a_lo[4];
#pragma unroll
            for (int hf = 0; hf < 2; hf++) {
                const int nt = 2 * ks + hf;
                const float p0 = accs[nt][0] * ps0;
                const float p1 = accs[nt][1] * ps0;
                const float p2 = accs[nt][2] * ps1;
                const float p3 = accs[nt][3] * ps1;
                __nv_bfloat16 h0 = __float2bfloat16_rn(p0);
                __nv_bfloat16 h1 = __float2bfloat16_rn(p1);
                __nv_bfloat16 h2 = __float2bfloat16_rn(p2);
                __nv_bfloat16 h3 = __float2bfloat16_rn(p3);
                a_hi[2 * hf + 0] = pack_bf16(h0, h1);
                a_hi[2 * hf + 1] = pack_bf16(h2, h3);
                a_lo[2 * hf + 0] = pack_bf16(
                    __float2bfloat16_rn(p0 - __bfloat162float(h0)),
                    __float2bfloat16_rn(p1 - __bfloat162float(h1)));
                a_lo[2 * hf + 1] = pack_bf16(
                    __float2bfloat16_rn(p2 - __bfloat162float(h2)),
                    __float2bfloat16_rn(p3 - __bfloat162float(h3)));
            }
            const uint32_t vrow = sb + (32 * wn + 16 * ks + (lane & 15)) * TST;
#pragma unroll
            for (int ng = 0; ng < 4; ng++) {
                uint32_t bth[4], btl[4];
                const uint32_t vaddr = vrow + (16 * ng + (lane >> 4) * 8) * 2;
                ldsm_x4_t(bth, vaddr + OFF_VHI);
                ldsm_x4_t(btl, vaddr + OFF_VLO);
                mma16816(O[2 * ng + 0], a_hi, bth[0], bth[1]);
                mma16816(O[2 * ng + 1], a_hi, bth[2], bth[3]);
                mma16816(O[2 * ng + 0], a_hi, btl[0], btl[1]);
                mma16816(O[2 * ng + 1], a_hi, btl[2], btl[3]);
                mma16816(O[2 * ng + 0], a_lo, bth[0], bth[1]);
                mma16816(O[2 * ng + 1], a_lo, bth[2], bth[3]);
            }
        }
    }

    // ---- epilogue: sum wn-pair partials via smem (alias QDS/KDST region) ----
    __syncthreads();
    if (wn == 0) {
        float* ob = (float*)(sm + OFF_QDS);
#pragma unroll
        for (int t = 0; t < 8; t++) {
            const int col = 8 * t + q2;
            *(float2*)&ob[wm * 1024 + (lane >> 2) * 64 + col] =
                make_float2(O[t][0], O[t][1]);
            *(float2*)&ob[wm * 1024 + ((lane >> 2) + 8) * 64 + col] =
                make_float2(O[t][2], O[t][3]);
        }
    }
    __syncthreads();
    if (wn == 1) {
        const float inv0 = 1.f / l0r;
        const float inv1 = 1.f / l1r;
        const float* ob = (const float*)(sm + OFF_QDS);
#pragma unroll
        for (int t = 0; t < 8; t++) {
            const int col = 8 * t + q2;
            float2 p0 = *(const float2*)&ob[wm * 1024 + (lane >> 2) * 64 + col];
            float2 p1 = *(const float2*)&ob[wm * 1024 + ((lane >> 2) + 8) * 64 + col];
            float2 o0 = make_float2((O[t][0] + p0.x) * inv0, (O[t][1] + p0.y) * inv0);
            float2 o1 = make_float2((O[t][2] + p1.x) * inv1, (O[t][3] + p1.y) * inv1);
            *(float2*)&out[((size_t)(b * SEQ) + l0g + lr0) * 1024 + h * 64 + col] = o0;
            *(float2*)&out[((size_t)(b * SEQ) + l0g + lr1) * 1024 + h * 64 + col] = o1;
        }
    }
}

// ---------------------------------------------------------------------------
extern "C" void kernel_launch(void* const* d_in, const int* in_sizes, int n_in,
                              void* d_out, int out_size) {
    const float* hs     = (const float*)d_in[0];  // [4,1024,1024]
    const float* qkv_w  = (const float*)d_in[1];  // [3072,1024]
    const float* qkv_b  = (const float*)d_in[2];  // [3072]
    const float* dist   = (const float*)d_in[3];  // [2047,64]
    const float* emask  = (const float*)d_in[4];  // [4,1,1,1024]
    float* out = (float*)d_out;

    cudaFuncSetAttribute(qkv_mma_kernel,
                         cudaFuncAttributeMaxDynamicSharedMemorySize, QKV_SMEM);
    dim3 g1(3072 / 128, 4096 / 128);
    qkv_mma_kernel<<<g1, 256, QKV_SMEM>>>(hs, qkv_w, qkv_b);

    cudaFuncSetAttribute(attn_mma_kernel,
                         cudaFuncAttributeMaxDynamicSharedMemorySize, ATTN_SMEM);
    dim3 g2(SEQ / 64, BHD);
    attn_mma_kernel<<<g2, 256, ATTN_SMEM>>>(dist, emask, out);
}